// round 1
// baseline (speedup 1.0000x reference)
#include <cuda_runtime.h>
#include <math.h>

// Problem constants (fixed shapes)
#define T_STEPS 12
#define N_NODES 50000
#define E_EDGES 800000
#define C_DIM   128
#define H_DIM   128

// ---------------- device scratch (no allocation allowed) ----------------
__device__ int   g_counts [N_NODES];
__device__ int   g_cursor [N_NODES];
__device__ int   g_offsets[N_NODES + 1];
__device__ int   g_csr    [E_EDGES];
__device__ float g_dinv   [N_NODES];
__device__ float g_bufA   [6400000];   // N_NODES * 128 : gemm output (dinv-scaled)
__device__ float g_bufB   [6400000];   // N_NODES * 128 : aggregated / relu'd features
__device__ float g_gseq   [T_STEPS * H_DIM];

// ---------------- small utility kernels ----------------
__global__ void zero_counts_kernel() {
    int i = blockIdx.x * blockDim.x + threadIdx.x;
    if (i < N_NODES) g_counts[i] = 0;
}

__global__ void zero_gseq_kernel() {
    int i = blockIdx.x * blockDim.x + threadIdx.x;
    if (i < T_STEPS * H_DIM) g_gseq[i] = 0.0f;
}

__global__ void count_kernel(const int* __restrict__ dst) {
    int i = blockIdx.x * blockDim.x + threadIdx.x;
    if (i < E_EDGES) atomicAdd(&g_counts[dst[i]], 1);
}

// single-block exclusive scan over g_counts -> g_offsets; also dinv + cursor reset
__global__ void scan_kernel() {
    __shared__ int warp_tot[32];
    __shared__ int chunk_base;
    int lane = threadIdx.x & 31;
    int wid  = threadIdx.x >> 5;
    if (threadIdx.x == 0) chunk_base = 0;
    __syncthreads();

    for (int base = 0; base < N_NODES; base += 1024) {
        int i = base + (int)threadIdx.x;
        int v = (i < N_NODES) ? g_counts[i] : 0;
        // inclusive warp scan
        int s = v;
        #pragma unroll
        for (int off = 1; off < 32; off <<= 1) {
            int u = __shfl_up_sync(0xFFFFFFFFu, s, off);
            if (lane >= off) s += u;
        }
        if (lane == 31) warp_tot[wid] = s;
        __syncthreads();
        if (wid == 0) {
            int w  = warp_tot[lane];
            int ws = w;
            #pragma unroll
            for (int off = 1; off < 32; off <<= 1) {
                int u = __shfl_up_sync(0xFFFFFFFFu, ws, off);
                if (lane >= off) ws += u;
            }
            warp_tot[lane] = ws - w;     // exclusive across warps
        }
        __syncthreads();
        int excl = chunk_base + warp_tot[wid] + (s - v);
        if (i < N_NODES) {
            g_offsets[i] = excl;
            g_cursor[i]  = 0;
            g_dinv[i]    = rsqrtf((float)(v + 1));   // +1 self-loop
        }
        __syncthreads();
        if (threadIdx.x == 1023) chunk_base += warp_tot[31] + s;
        __syncthreads();
    }
    if (threadIdx.x == 0) g_offsets[N_NODES] = chunk_base;
}

__global__ void fill_kernel(const int* __restrict__ src, const int* __restrict__ dst) {
    int i = blockIdx.x * blockDim.x + threadIdx.x;
    if (i < E_EDGES) {
        int d   = dst[i];
        int pos = g_offsets[d] + atomicAdd(&g_cursor[d], 1);
        g_csr[pos] = src[i];
    }
}

// ---------------- SGEMM:  Y = diag(dinv) * (A[M,128] @ B[128,128]) ----------------
// BM=128, BN=128, BK=8; 256 threads; each thread: 8x8 outputs in split 4+4 tiles.
__global__ void gemm_scale_kernel(const float* __restrict__ A,
                                  const float* __restrict__ B,
                                  float* __restrict__ Y, int M)
{
    __shared__ float As[8][128];
    __shared__ float Bs[8][128];

    int tid  = threadIdx.x;           // 0..255
    int tx   = tid & 15;              // col group
    int ty   = tid >> 4;              // row group
    int row0 = blockIdx.x * 128;

    float acc[8][8];
    #pragma unroll
    for (int i = 0; i < 8; i++)
        #pragma unroll
        for (int j = 0; j < 8; j++) acc[i][j] = 0.0f;

    for (int k0 = 0; k0 < 128; k0 += 8) {
        #pragma unroll
        for (int i = 0; i < 4; i++) {
            int idx = tid + i * 256;
            int m   = idx >> 3;
            int kk  = idx & 7;
            int gr  = row0 + m;
            As[kk][m] = (gr < M) ? A[(size_t)gr * 128 + k0 + kk] : 0.0f;
        }
        #pragma unroll
        for (int i = 0; i < 4; i++) {
            int idx = tid + i * 256;
            int kk  = idx >> 7;
            int nn  = idx & 127;
            Bs[kk][nn] = B[(size_t)(k0 + kk) * 128 + nn];
        }
        __syncthreads();

        #pragma unroll
        for (int kk = 0; kk < 8; kk++) {
            float ra[8], rb[8];
            *(float4*)&ra[0] = *(const float4*)&As[kk][ty * 4];
            *(float4*)&ra[4] = *(const float4*)&As[kk][64 + ty * 4];
            *(float4*)&rb[0] = *(const float4*)&Bs[kk][tx * 4];
            *(float4*)&rb[4] = *(const float4*)&Bs[kk][64 + tx * 4];
            #pragma unroll
            for (int i = 0; i < 8; i++)
                #pragma unroll
                for (int j = 0; j < 8; j++)
                    acc[i][j] = fmaf(ra[i], rb[j], acc[i][j]);
        }
        __syncthreads();
    }

    #pragma unroll
    for (int gi = 0; gi < 2; gi++) {
        #pragma unroll
        for (int ii = 0; ii < 4; ii++) {
            int r = row0 + gi * 64 + ty * 4 + ii;
            if (r < M) {
                float d = g_dinv[r];
                int ai  = gi * 4 + ii;
                float4 o0, o1;
                o0.x = d * acc[ai][0]; o0.y = d * acc[ai][1];
                o0.z = d * acc[ai][2]; o0.w = d * acc[ai][3];
                o1.x = d * acc[ai][4]; o1.y = d * acc[ai][5];
                o1.z = d * acc[ai][6]; o1.w = d * acc[ai][7];
                *(float4*)&Y[(size_t)r * 128 + tx * 4]      = o0;
                *(float4*)&Y[(size_t)r * 128 + 64 + tx * 4] = o1;
            }
        }
    }
}

// ---------------- aggregation: out[i] = relu(dinv[i]*(h'[i] + sum_{src->i} h'[src]) + b)
// one warp per node, float4 per lane (32*4 = 128 floats)
__global__ void agg_kernel(const float* __restrict__ hp,
                           const float* __restrict__ bias,
                           float* __restrict__ out)
{
    int warp_id = (blockIdx.x * blockDim.x + threadIdx.x) >> 5;
    int lane    = threadIdx.x & 31;
    if (warp_id >= N_NODES) return;

    float4 a = ((const float4*)(hp + (size_t)warp_id * 128))[lane];  // self loop
    int s = g_offsets[warp_id];
    int e = g_offsets[warp_id + 1];
    for (int j = s; j < e; j++) {
        int src = __ldg(&g_csr[j]);
        float4 v = ((const float4*)(hp + (size_t)src * 128))[lane];
        a.x += v.x; a.y += v.y; a.z += v.z; a.w += v.w;
    }
    float  d = g_dinv[warp_id];
    float4 b = ((const float4*)bias)[lane];
    float4 r;
    r.x = fmaxf(fmaf(d, a.x, b.x), 0.0f);
    r.y = fmaxf(fmaf(d, a.y, b.y), 0.0f);
    r.z = fmaxf(fmaf(d, a.z, b.z), 0.0f);
    r.w = fmaxf(fmaf(d, a.w, b.w), 0.0f);
    ((float4*)(out + (size_t)warp_id * 128))[lane] = r;
}

// ---------------- mean pool over nodes -> g_gseq[t] ----------------
__global__ void pool_kernel(const float* __restrict__ h2, int t)
{
    int col = threadIdx.x;   // 128
    float acc = 0.0f;
    for (int r = blockIdx.x; r < N_NODES; r += gridDim.x)
        acc += h2[(size_t)r * 128 + col];
    atomicAdd(&g_gseq[t * H_DIM + col], acc * (1.0f / (float)N_NODES));
}

// ---------------- GRU over T steps + head (single block, 128 threads) ----------------
__global__ void gru_head_kernel(const float* __restrict__ W_ih,
                                const float* __restrict__ W_hh,
                                const float* __restrict__ b_ih,
                                const float* __restrict__ b_hh,
                                const float* __restrict__ W_head,
                                const float* __restrict__ b_head,
                                float* __restrict__ out)
{
    __shared__ float gbuf[128];
    __shared__ float hbuf[128];
    int j = threadIdx.x;
    hbuf[j] = 0.0f;
    __syncthreads();

    for (int t = 0; t < T_STEPS; t++) {
        gbuf[j] = g_gseq[t * H_DIM + j];
        __syncthreads();
        float gir = b_ih[j], giz = b_ih[128 + j], gin = b_ih[256 + j];
        float ghr = b_hh[j], ghz = b_hh[128 + j], ghn = b_hh[256 + j];
        const float* wi0 = W_ih + (size_t)j * 128;
        const float* wi1 = W_ih + (size_t)(128 + j) * 128;
        const float* wi2 = W_ih + (size_t)(256 + j) * 128;
        const float* wh0 = W_hh + (size_t)j * 128;
        const float* wh1 = W_hh + (size_t)(128 + j) * 128;
        const float* wh2 = W_hh + (size_t)(256 + j) * 128;
        #pragma unroll 4
        for (int k = 0; k < 128; k++) {
            float gk = gbuf[k], hk = hbuf[k];
            gir = fmaf(wi0[k], gk, gir);
            giz = fmaf(wi1[k], gk, giz);
            gin = fmaf(wi2[k], gk, gin);
            ghr = fmaf(wh0[k], hk, ghr);
            ghz = fmaf(wh1[k], hk, ghz);
            ghn = fmaf(wh2[k], hk, ghn);
        }
        float r  = 1.0f / (1.0f + expf(-(gir + ghr)));
        float z  = 1.0f / (1.0f + expf(-(giz + ghz)));
        float nn = tanhf(gin + r * ghn);
        float hn = (1.0f - z) * nn + z * hbuf[j];
        __syncthreads();
        hbuf[j] = hn;
        __syncthreads();
    }

    float o = b_head[j];
    const float* wr = W_head + (size_t)j * 128;
    #pragma unroll 4
    for (int k = 0; k < 128; k++) o = fmaf(wr[k], hbuf[k], o);
    out[j] = o;
}

// ---------------- launch ----------------
extern "C" void kernel_launch(void* const* d_in, const int* in_sizes, int n_in,
                              void* d_out, int out_size)
{
    const float* x_seq  = (const float*)d_in[0];
    const int*   ei_seq = (const int*)  d_in[1];
    const float* W1     = (const float*)d_in[2];
    const float* b1     = (const float*)d_in[3];
    const float* W2     = (const float*)d_in[4];
    const float* b2     = (const float*)d_in[5];
    const float* W_ih   = (const float*)d_in[6];
    const float* W_hh   = (const float*)d_in[7];
    const float* b_ih   = (const float*)d_in[8];
    const float* b_hh   = (const float*)d_in[9];
    const float* W_head = (const float*)d_in[10];
    const float* b_head = (const float*)d_in[11];
    float* out = (float*)d_out;

    // symbol addresses for kernel params
    float* bufA; cudaGetSymbolAddress((void**)&bufA, g_bufA);
    float* bufB; cudaGetSymbolAddress((void**)&bufB, g_bufB);

    const int EB = (E_EDGES + 255) / 256;
    const int NB = (N_NODES + 255) / 256;
    const int GM = (N_NODES + 127) / 128;          // gemm blocks
    const int AG = (N_NODES * 32 + 255) / 256;     // agg blocks (warp/node)

    zero_gseq_kernel<<<(T_STEPS * H_DIM + 255) / 256, 256>>>();

    for (int t = 0; t < T_STEPS; t++) {
        const float* x_t   = x_seq  + (size_t)t * N_NODES * C_DIM;
        const int*   src_t = ei_seq + (size_t)t * 2 * E_EDGES;
        const int*   dst_t = src_t + E_EDGES;

        zero_counts_kernel<<<NB, 256>>>();
        count_kernel<<<EB, 256>>>(dst_t);
        scan_kernel<<<1, 1024>>>();
        fill_kernel<<<EB, 256>>>(src_t, dst_t);

        // layer 1
        gemm_scale_kernel<<<GM, 256>>>(x_t, W1, bufA, N_NODES);
        agg_kernel<<<AG, 256>>>(bufA, b1, bufB);
        // layer 2
        gemm_scale_kernel<<<GM, 256>>>(bufB, W2, bufA, N_NODES);
        agg_kernel<<<AG, 256>>>(bufA, b2, bufB);
        // mean pool
        pool_kernel<<<296, 128>>>(bufB, t);
    }

    gru_head_kernel<<<1, 128>>>(W_ih, W_hh, b_ih, b_hh, W_head, b_head, out);
}

// round 2
// speedup vs baseline: 1.4275x; 1.4275x over previous
#include <cuda_runtime.h>
#include <math.h>

#define T_STEPS 12
#define N_NODES 50000
#define E_EDGES 800000
#define C_DIM   128
#define H_DIM   128

#define TOTAL_CNT (T_STEPS * N_NODES)            // 600000
#define NB_SCAN   ((TOTAL_CNT + 1023) / 1024)    // 586

// ---------------- device scratch ----------------
__device__ int   g_counts [TOTAL_CNT];
__device__ int   g_cursor [TOTAL_CNT];
__device__ int   g_offsets[TOTAL_CNT + 1];
__device__ int   g_bsums  [1024];
__device__ int   g_bbase  [1024];
__device__ int   g_csr    [T_STEPS * E_EDGES];   // 9.6M
__device__ float g_dinv   [TOTAL_CNT];
__device__ float g_bufA   [6400000];             // N*128
__device__ float g_bufB   [6400000];             // N*128
__device__ float g_gseq   [T_STEPS * H_DIM];

// ---------------- zero everything that needs it ----------------
__global__ void zero_all_kernel() {
    int i = blockIdx.x * blockDim.x + threadIdx.x;
    if (i < TOTAL_CNT) { g_counts[i] = 0; g_cursor[i] = 0; }
    if (i < T_STEPS * H_DIM) g_gseq[i] = 0.0f;
}

// ---------------- count degrees for all 12 timesteps ----------------
__global__ void count_all_kernel(const int* __restrict__ ei_seq) {
    int g = blockIdx.x * blockDim.x + threadIdx.x;
    if (g >= T_STEPS * E_EDGES) return;
    int t = g / E_EDGES;
    int e = g - t * E_EDGES;
    int d = ei_seq[(size_t)t * 2 * E_EDGES + E_EDGES + e];
    atomicAdd(&g_counts[t * N_NODES + d], 1);
}

// ---------------- hierarchical scan: S1 (block-local) ----------------
__global__ void scan1_kernel() {
    __shared__ int wt[32];
    int lane = threadIdx.x & 31;
    int wid  = threadIdx.x >> 5;
    int gid  = blockIdx.x * 1024 + threadIdx.x;
    int v = (gid < TOTAL_CNT) ? g_counts[gid] : 0;
    int s = v;
    #pragma unroll
    for (int off = 1; off < 32; off <<= 1) {
        int u = __shfl_up_sync(0xFFFFFFFFu, s, off);
        if (lane >= off) s += u;
    }
    if (lane == 31) wt[wid] = s;
    __syncthreads();
    if (wid == 0) {
        int w = wt[lane];
        int ws = w;
        #pragma unroll
        for (int off = 1; off < 32; off <<= 1) {
            int u = __shfl_up_sync(0xFFFFFFFFu, ws, off);
            if (lane >= off) ws += u;
        }
        wt[lane] = ws - w;   // exclusive across warps
    }
    __syncthreads();
    int excl = wt[wid] + (s - v);
    if (gid < TOTAL_CNT) {
        g_offsets[gid] = excl;
        g_dinv[gid]    = rsqrtf((float)(v + 1));
    }
    if (threadIdx.x == 1023) g_bsums[blockIdx.x] = excl + v;
}

// ---------------- S2: scan block sums (single block) ----------------
__global__ void scan2_kernel() {
    __shared__ int wt[32];
    int lane = threadIdx.x & 31;
    int wid  = threadIdx.x >> 5;
    int i = threadIdx.x;
    int v = (i < NB_SCAN) ? g_bsums[i] : 0;
    int s = v;
    #pragma unroll
    for (int off = 1; off < 32; off <<= 1) {
        int u = __shfl_up_sync(0xFFFFFFFFu, s, off);
        if (lane >= off) s += u;
    }
    if (lane == 31) wt[wid] = s;
    __syncthreads();
    if (wid == 0) {
        int w = wt[lane];
        int ws = w;
        #pragma unroll
        for (int off = 1; off < 32; off <<= 1) {
            int u = __shfl_up_sync(0xFFFFFFFFu, ws, off);
            if (lane >= off) ws += u;
        }
        wt[lane] = ws - w;
    }
    __syncthreads();
    g_bbase[i] = wt[wid] + (s - v);
}

// ---------------- S3: add block bases ----------------
__global__ void scan3_kernel() {
    int gid = blockIdx.x * 1024 + threadIdx.x;
    if (gid < TOTAL_CNT) g_offsets[gid] += g_bbase[blockIdx.x];
    if (gid == 0) g_offsets[TOTAL_CNT] = T_STEPS * E_EDGES;
}

// ---------------- fill CSR for all timesteps ----------------
__global__ void fill_all_kernel(const int* __restrict__ ei_seq) {
    int g = blockIdx.x * blockDim.x + threadIdx.x;
    if (g >= T_STEPS * E_EDGES) return;
    int t = g / E_EDGES;
    int e = g - t * E_EDGES;
    const int* base = ei_seq + (size_t)t * 2 * E_EDGES;
    int sv = base[e];
    int dv = base[E_EDGES + e];
    int f  = t * N_NODES + dv;
    int pos = g_offsets[f] + atomicAdd(&g_cursor[f], 1);
    g_csr[pos] = sv;
}

// ---------------- SGEMM: Y = diag(dinv) * (A[M,128] @ B[128,128]) ----------------
__global__ void gemm_scale_kernel(const float* __restrict__ A,
                                  const float* __restrict__ B,
                                  const float* __restrict__ dinv,
                                  float* __restrict__ Y, int M)
{
    __shared__ float As[8][128];
    __shared__ float Bs[8][128];

    int tid  = threadIdx.x;           // 0..255
    int tx   = tid & 15;
    int ty   = tid >> 4;
    int row0 = blockIdx.x * 128;

    float acc[8][8];
    #pragma unroll
    for (int i = 0; i < 8; i++)
        #pragma unroll
        for (int j = 0; j < 8; j++) acc[i][j] = 0.0f;

    // load indices (float4)
    int am = tid >> 1;                // row within tile
    int ak = (tid & 1) * 4;           // k offset within BK=8

    for (int k0 = 0; k0 < 128; k0 += 8) {
        // A tile: 128 rows x 8 k = 256 float4
        {
            int gr = row0 + am;
            float4 v = make_float4(0.f, 0.f, 0.f, 0.f);
            if (gr < M) v = *(const float4*)&A[(size_t)gr * 128 + k0 + ak];
            As[ak + 0][am] = v.x;
            As[ak + 1][am] = v.y;
            As[ak + 2][am] = v.z;
            As[ak + 3][am] = v.w;
        }
        // B tile: 8 k x 128 n = 256 float4, same layout -> flat copy
        ((float4*)Bs)[tid] = *(const float4*)&B[(size_t)k0 * 128 + tid * 4];
        __syncthreads();

        #pragma unroll
        for (int kk = 0; kk < 8; kk++) {
            float ra[8], rb[8];
            *(float4*)&ra[0] = *(const float4*)&As[kk][ty * 4];
            *(float4*)&ra[4] = *(const float4*)&As[kk][64 + ty * 4];
            *(float4*)&rb[0] = *(const float4*)&Bs[kk][tx * 4];
            *(float4*)&rb[4] = *(const float4*)&Bs[kk][64 + tx * 4];
            #pragma unroll
            for (int i = 0; i < 8; i++)
                #pragma unroll
                for (int j = 0; j < 8; j++)
                    acc[i][j] = fmaf(ra[i], rb[j], acc[i][j]);
        }
        __syncthreads();
    }

    #pragma unroll
    for (int gi = 0; gi < 2; gi++) {
        #pragma unroll
        for (int ii = 0; ii < 4; ii++) {
            int r = row0 + gi * 64 + ty * 4 + ii;
            if (r < M) {
                float d = dinv[r];
                int ai  = gi * 4 + ii;
                float4 o0, o1;
                o0.x = d * acc[ai][0]; o0.y = d * acc[ai][1];
                o0.z = d * acc[ai][2]; o0.w = d * acc[ai][3];
                o1.x = d * acc[ai][4]; o1.y = d * acc[ai][5];
                o1.z = d * acc[ai][6]; o1.w = d * acc[ai][7];
                *(float4*)&Y[(size_t)r * 128 + tx * 4]      = o0;
                *(float4*)&Y[(size_t)r * 128 + 64 + tx * 4] = o1;
            }
        }
    }
}

// ---------------- layer-1 aggregation: warp per node ----------------
__global__ void agg_kernel(const float* __restrict__ hp,
                           const float* __restrict__ bias,
                           const float* __restrict__ dinv,
                           const int* __restrict__ offs,
                           float* __restrict__ out)
{
    int warp_id = (blockIdx.x * blockDim.x + threadIdx.x) >> 5;
    int lane    = threadIdx.x & 31;
    if (warp_id >= N_NODES) return;

    float4 a = ((const float4*)(hp + (size_t)warp_id * 128))[lane];  // self loop
    int s = offs[warp_id];
    int e = offs[warp_id + 1];
    for (int j = s; j < e; j++) {
        int src = __ldg(&g_csr[j]);
        float4 v = ((const float4*)(hp + (size_t)src * 128))[lane];
        a.x += v.x; a.y += v.y; a.z += v.z; a.w += v.w;
    }
    float  d = dinv[warp_id];
    float4 b = ((const float4*)bias)[lane];
    float4 r;
    r.x = fmaxf(fmaf(d, a.x, b.x), 0.0f);
    r.y = fmaxf(fmaf(d, a.y, b.y), 0.0f);
    r.z = fmaxf(fmaf(d, a.z, b.z), 0.0f);
    r.w = fmaxf(fmaf(d, a.w, b.w), 0.0f);
    ((float4*)(out + (size_t)warp_id * 128))[lane] = r;
}

// ---------------- layer-2 aggregation fused with mean pool ----------------
// grid-strided warp-per-node; pooled sum accumulated in registers,
// reduced via shared then atomically added to g_gseq[t].
__global__ void agg_pool_kernel(const float* __restrict__ hp,
                                const float* __restrict__ bias,
                                const float* __restrict__ dinv,
                                const int* __restrict__ offs,
                                float* __restrict__ gt)
{
    __shared__ float sacc[128];
    int lane  = threadIdx.x & 31;
    int wid   = threadIdx.x >> 5;                  // warp in block (0..7)
    int gwarp = blockIdx.x * 8 + wid;
    int nwarps = gridDim.x * 8;

    if (threadIdx.x < 128) sacc[threadIdx.x] = 0.0f;
    __syncthreads();

    float4 b = ((const float4*)bias)[lane];
    float4 pool = make_float4(0.f, 0.f, 0.f, 0.f);

    for (int node = gwarp; node < N_NODES; node += nwarps) {
        float4 a = ((const float4*)(hp + (size_t)node * 128))[lane];
        int s = offs[node];
        int e = offs[node + 1];
        for (int j = s; j < e; j++) {
            int src = __ldg(&g_csr[j]);
            float4 v = ((const float4*)(hp + (size_t)src * 128))[lane];
            a.x += v.x; a.y += v.y; a.z += v.z; a.w += v.w;
        }
        float d = dinv[node];
        pool.x += fmaxf(fmaf(d, a.x, b.x), 0.0f);
        pool.y += fmaxf(fmaf(d, a.y, b.y), 0.0f);
        pool.z += fmaxf(fmaf(d, a.z, b.z), 0.0f);
        pool.w += fmaxf(fmaf(d, a.w, b.w), 0.0f);
    }

    atomicAdd(&sacc[lane * 4 + 0], pool.x);
    atomicAdd(&sacc[lane * 4 + 1], pool.y);
    atomicAdd(&sacc[lane * 4 + 2], pool.z);
    atomicAdd(&sacc[lane * 4 + 3], pool.w);
    __syncthreads();
    if (threadIdx.x < 128)
        atomicAdd(&gt[threadIdx.x], sacc[threadIdx.x] * (1.0f / (float)N_NODES));
}

// ---------------- GRU over T steps + head ----------------
__global__ void gru_head_kernel(const float* __restrict__ W_ih,
                                const float* __restrict__ W_hh,
                                const float* __restrict__ b_ih,
                                const float* __restrict__ b_hh,
                                const float* __restrict__ W_head,
                                const float* __restrict__ b_head,
                                float* __restrict__ out)
{
    __shared__ float gbuf[128];
    __shared__ float hbuf[128];
    int j = threadIdx.x;
    hbuf[j] = 0.0f;
    __syncthreads();

    for (int t = 0; t < T_STEPS; t++) {
        gbuf[j] = g_gseq[t * H_DIM + j];
        __syncthreads();
        float gir = b_ih[j], giz = b_ih[128 + j], gin = b_ih[256 + j];
        float ghr = b_hh[j], ghz = b_hh[128 + j], ghn = b_hh[256 + j];
        const float* wi0 = W_ih + (size_t)j * 128;
        const float* wi1 = W_ih + (size_t)(128 + j) * 128;
        const float* wi2 = W_ih + (size_t)(256 + j) * 128;
        const float* wh0 = W_hh + (size_t)j * 128;
        const float* wh1 = W_hh + (size_t)(128 + j) * 128;
        const float* wh2 = W_hh + (size_t)(256 + j) * 128;
        #pragma unroll 4
        for (int k = 0; k < 128; k++) {
            float gk = gbuf[k], hk = hbuf[k];
            gir = fmaf(wi0[k], gk, gir);
            giz = fmaf(wi1[k], gk, giz);
            gin = fmaf(wi2[k], gk, gin);
            ghr = fmaf(wh0[k], hk, ghr);
            ghz = fmaf(wh1[k], hk, ghz);
            ghn = fmaf(wh2[k], hk, ghn);
        }
        float r  = 1.0f / (1.0f + expf(-(gir + ghr)));
        float z  = 1.0f / (1.0f + expf(-(giz + ghz)));
        float nn = tanhf(gin + r * ghn);
        float hn = (1.0f - z) * nn + z * hbuf[j];
        __syncthreads();
        hbuf[j] = hn;
        __syncthreads();
    }

    float o = b_head[j];
    const float* wr = W_head + (size_t)j * 128;
    #pragma unroll 4
    for (int k = 0; k < 128; k++) o = fmaf(wr[k], hbuf[k], o);
    out[j] = o;
}

// ---------------- launch ----------------
extern "C" void kernel_launch(void* const* d_in, const int* in_sizes, int n_in,
                              void* d_out, int out_size)
{
    const float* x_seq  = (const float*)d_in[0];
    const int*   ei_seq = (const int*)  d_in[1];
    const float* W1     = (const float*)d_in[2];
    const float* b1     = (const float*)d_in[3];
    const float* W2     = (const float*)d_in[4];
    const float* b2     = (const float*)d_in[5];
    const float* W_ih   = (const float*)d_in[6];
    const float* W_hh   = (const float*)d_in[7];
    const float* b_ih   = (const float*)d_in[8];
    const float* b_hh   = (const float*)d_in[9];
    const float* W_head = (const float*)d_in[10];
    const float* b_head = (const float*)d_in[11];
    float* out = (float*)d_out;

    float* bufA;   cudaGetSymbolAddress((void**)&bufA, g_bufA);
    float* bufB;   cudaGetSymbolAddress((void**)&bufB, g_bufB);
    float* dinv;   cudaGetSymbolAddress((void**)&dinv, g_dinv);
    int*   offs;   cudaGetSymbolAddress((void**)&offs, g_offsets);
    float* gseq;   cudaGetSymbolAddress((void**)&gseq, g_gseq);

    const int GEB = (T_STEPS * E_EDGES + 255) / 256;   // all-t edge grid
    const int GM  = (N_NODES + 127) / 128;             // gemm blocks
    const int AG  = (N_NODES * 32 + 255) / 256;        // agg blocks
    const int APB = 1480;                              // agg_pool blocks

    // ---- CSR build for all timesteps (batched) ----
    zero_all_kernel<<<(TOTAL_CNT + 255) / 256, 256>>>();          // #0
    count_all_kernel<<<GEB, 256>>>(ei_seq);                        // #1
    scan1_kernel<<<NB_SCAN, 1024>>>();                             // #2
    scan2_kernel<<<1, 1024>>>();                                   // #3
    scan3_kernel<<<NB_SCAN, 1024>>>();                             // #4

    // launch #5 = GEMM (profiled by ncu -s 5 -c 1)
    gemm_scale_kernel<<<GM, 256>>>(x_seq, W1, dinv, bufA, N_NODES);  // t=0 layer1

    fill_all_kernel<<<GEB, 256>>>(ei_seq);                         // #6

    for (int t = 0; t < T_STEPS; t++) {
        const float* x_t    = x_seq + (size_t)t * N_NODES * C_DIM;
        const float* dinv_t = dinv + t * N_NODES;
        const int*   offs_t = offs + t * N_NODES;

        if (t > 0)
            gemm_scale_kernel<<<GM, 256>>>(x_t, W1, dinv_t, bufA, N_NODES);
        agg_kernel<<<AG, 256>>>(bufA, b1, dinv_t, offs_t, bufB);
        gemm_scale_kernel<<<GM, 256>>>(bufB, W2, dinv_t, bufA, N_NODES);
        agg_pool_kernel<<<APB, 256>>>(bufA, b2, dinv_t, offs_t, gseq + t * H_DIM);
    }

    gru_head_kernel<<<1, 128>>>(W_ih, W_hh, b_ih, b_hh, W_head, b_head, out);
}

// round 3
// speedup vs baseline: 1.7411x; 1.2196x over previous
#include <cuda_runtime.h>
#include <math.h>

#define T_STEPS 12
#define N_NODES 50000
#define E_EDGES 800000
#define C_DIM   128
#define H_DIM   128

#define TOTAL_CNT  (T_STEPS * N_NODES)            // 600000
#define TOTAL_ROWS (T_STEPS * N_NODES)            // 600000 flat rows
#define NB_SCAN    ((TOTAL_CNT + 1023) / 1024)    // 586

// ---------------- device scratch ----------------
__device__ int   g_counts [TOTAL_CNT];
__device__ int   g_cursor [TOTAL_CNT];
__device__ int   g_offsets[TOTAL_CNT + 1];
__device__ int   g_bsums  [1024];
__device__ int   g_bbase  [1024];
__device__ int   g_csr    [T_STEPS * E_EDGES];        // 9.6M
__device__ float g_dinv   [TOTAL_CNT];
__device__ float g_bufA   [TOTAL_ROWS * 128];         // 307 MB
__device__ float g_bufB   [TOTAL_ROWS * 128];         // 307 MB
__device__ float g_gseq   [T_STEPS * H_DIM];

// ---------------- zero counters / gseq ----------------
__global__ void zero_all_kernel() {
    int i = blockIdx.x * blockDim.x + threadIdx.x;
    if (i < TOTAL_CNT) { g_counts[i] = 0; g_cursor[i] = 0; }
    if (i < T_STEPS * H_DIM) g_gseq[i] = 0.0f;
}

// ---------------- count degrees (all timesteps) ----------------
__global__ void count_all_kernel(const int* __restrict__ ei_seq) {
    int g = blockIdx.x * blockDim.x + threadIdx.x;
    if (g >= T_STEPS * E_EDGES) return;
    int t = g / E_EDGES;
    int e = g - t * E_EDGES;
    int d = ei_seq[(size_t)t * 2 * E_EDGES + E_EDGES + e];
    atomicAdd(&g_counts[t * N_NODES + d], 1);
}

// ---------------- hierarchical scan ----------------
__global__ void scan1_kernel() {
    __shared__ int wt[32];
    int lane = threadIdx.x & 31;
    int wid  = threadIdx.x >> 5;
    int gid  = blockIdx.x * 1024 + threadIdx.x;
    int v = (gid < TOTAL_CNT) ? g_counts[gid] : 0;
    int s = v;
    #pragma unroll
    for (int off = 1; off < 32; off <<= 1) {
        int u = __shfl_up_sync(0xFFFFFFFFu, s, off);
        if (lane >= off) s += u;
    }
    if (lane == 31) wt[wid] = s;
    __syncthreads();
    if (wid == 0) {
        int w = wt[lane];
        int ws = w;
        #pragma unroll
        for (int off = 1; off < 32; off <<= 1) {
            int u = __shfl_up_sync(0xFFFFFFFFu, ws, off);
            if (lane >= off) ws += u;
        }
        wt[lane] = ws - w;
    }
    __syncthreads();
    int excl = wt[wid] + (s - v);
    if (gid < TOTAL_CNT) {
        g_offsets[gid] = excl;
        g_dinv[gid]    = rsqrtf((float)(v + 1));
    }
    if (threadIdx.x == 1023) g_bsums[blockIdx.x] = excl + v;
}

__global__ void scan2_kernel() {
    __shared__ int wt[32];
    int lane = threadIdx.x & 31;
    int wid  = threadIdx.x >> 5;
    int i = threadIdx.x;
    int v = (i < NB_SCAN) ? g_bsums[i] : 0;
    int s = v;
    #pragma unroll
    for (int off = 1; off < 32; off <<= 1) {
        int u = __shfl_up_sync(0xFFFFFFFFu, s, off);
        if (lane >= off) s += u;
    }
    if (lane == 31) wt[wid] = s;
    __syncthreads();
    if (wid == 0) {
        int w = wt[lane];
        int ws = w;
        #pragma unroll
        for (int off = 1; off < 32; off <<= 1) {
            int u = __shfl_up_sync(0xFFFFFFFFu, ws, off);
            if (lane >= off) ws += u;
        }
        wt[lane] = ws - w;
    }
    __syncthreads();
    g_bbase[i] = wt[wid] + (s - v);
}

__global__ void scan3_kernel() {
    int gid = blockIdx.x * 1024 + threadIdx.x;
    if (gid < TOTAL_CNT) g_offsets[gid] += g_bbase[blockIdx.x];
    if (gid == 0) g_offsets[TOTAL_CNT] = T_STEPS * E_EDGES;
}

// ---------------- fill CSR (all timesteps) ----------------
__global__ void fill_all_kernel(const int* __restrict__ ei_seq) {
    int g = blockIdx.x * blockDim.x + threadIdx.x;
    if (g >= T_STEPS * E_EDGES) return;
    int t = g / E_EDGES;
    int e = g - t * E_EDGES;
    const int* base = ei_seq + (size_t)t * 2 * E_EDGES;
    int sv = base[e];
    int dv = base[E_EDGES + e];
    int f  = t * N_NODES + dv;
    int pos = g_offsets[f] + atomicAdd(&g_cursor[f], 1);
    g_csr[pos] = sv;
}

// ---------------- SGEMM (batched over flat M): Y = diag(dinv) * (A @ B) ----------------
// 128x128 tile, BK=8, 256 threads, 8x8/thread, register double-buffered loads.
__global__ void gemm_scale_kernel(const float* __restrict__ A,
                                  const float* __restrict__ B,
                                  const float* __restrict__ dinv,
                                  float* __restrict__ Y, int M)
{
    __shared__ float As[8][128];
    __shared__ float Bs[8][128];

    int tid  = threadIdx.x;           // 0..255
    int tx   = tid & 15;
    int ty   = tid >> 4;
    int row0 = blockIdx.x * 128;

    float acc[8][8];
    #pragma unroll
    for (int i = 0; i < 8; i++)
        #pragma unroll
        for (int j = 0; j < 8; j++) acc[i][j] = 0.0f;

    int am = tid >> 1;                // A row within tile
    int ak = (tid & 1) * 4;           // A k offset within BK=8
    int agr = row0 + am;
    bool arow_ok = (agr < M);
    const float* Aptr = A + (size_t)agr * 128 + ak;

    // prefetch k0 = 0
    float4 a_next = make_float4(0.f, 0.f, 0.f, 0.f);
    if (arow_ok) a_next = *(const float4*)Aptr;
    float4 b_next = *(const float4*)&B[tid * 4];

    for (int k0 = 0; k0 < 128; k0 += 8) {
        As[ak + 0][am] = a_next.x;
        As[ak + 1][am] = a_next.y;
        As[ak + 2][am] = a_next.z;
        As[ak + 3][am] = a_next.w;
        ((float4*)Bs)[tid] = b_next;
        __syncthreads();

        if (k0 + 8 < 128) {
            if (arow_ok) a_next = *(const float4*)(Aptr + k0 + 8);
            b_next = *(const float4*)&B[(size_t)(k0 + 8) * 128 + tid * 4];
        }

        #pragma unroll
        for (int kk = 0; kk < 8; kk++) {
            float ra[8], rb[8];
            *(float4*)&ra[0] = *(const float4*)&As[kk][ty * 4];
            *(float4*)&ra[4] = *(const float4*)&As[kk][64 + ty * 4];
            *(float4*)&rb[0] = *(const float4*)&Bs[kk][tx * 4];
            *(float4*)&rb[4] = *(const float4*)&Bs[kk][64 + tx * 4];
            #pragma unroll
            for (int i = 0; i < 8; i++)
                #pragma unroll
                for (int j = 0; j < 8; j++)
                    acc[i][j] = fmaf(ra[i], rb[j], acc[i][j]);
        }
        __syncthreads();
    }

    #pragma unroll
    for (int gi = 0; gi < 2; gi++) {
        #pragma unroll
        for (int ii = 0; ii < 4; ii++) {
            int r = row0 + gi * 64 + ty * 4 + ii;
            if (r < M) {
                float d = dinv[r];
                int ai  = gi * 4 + ii;
                float4 o0, o1;
                o0.x = d * acc[ai][0]; o0.y = d * acc[ai][1];
                o0.z = d * acc[ai][2]; o0.w = d * acc[ai][3];
                o1.x = d * acc[ai][4]; o1.y = d * acc[ai][5];
                o1.z = d * acc[ai][6]; o1.w = d * acc[ai][7];
                *(float4*)&Y[(size_t)r * 128 + tx * 4]      = o0;
                *(float4*)&Y[(size_t)r * 128 + 64 + tx * 4] = o1;
            }
        }
    }
}

// ---------------- batched layer-1 aggregation: gridDim.y = t, warp per node ----------------
__global__ void agg_kernel(const float* __restrict__ hpAll,
                           const float* __restrict__ bias,
                           const float* __restrict__ dinvAll,
                           const int* __restrict__ offsAll,
                           float* __restrict__ outAll)
{
    int t = blockIdx.y;
    int node = (blockIdx.x * blockDim.x + threadIdx.x) >> 5;
    int lane = threadIdx.x & 31;
    if (node >= N_NODES) return;

    const float* hp   = hpAll   + (size_t)t * N_NODES * 128;
    const float* dinv = dinvAll + (size_t)t * N_NODES;
    const int*   offs = offsAll + (size_t)t * N_NODES;
    float*       out  = outAll  + (size_t)t * N_NODES * 128;

    float4 a = ((const float4*)(hp + (size_t)node * 128))[lane];  // self loop
    int s = offs[node];
    int e = offs[node + 1];
    for (int j = s; j < e; j++) {
        int src = __ldg(&g_csr[j]);
        float4 v = ((const float4*)(hp + (size_t)src * 128))[lane];
        a.x += v.x; a.y += v.y; a.z += v.z; a.w += v.w;
    }
    float  d = dinv[node];
    float4 b = ((const float4*)bias)[lane];
    float4 r;
    r.x = fmaxf(fmaf(d, a.x, b.x), 0.0f);
    r.y = fmaxf(fmaf(d, a.y, b.y), 0.0f);
    r.z = fmaxf(fmaf(d, a.z, b.z), 0.0f);
    r.w = fmaxf(fmaf(d, a.w, b.w), 0.0f);
    ((float4*)(out + (size_t)node * 128))[lane] = r;
}

// ---------------- batched layer-2 agg + mean pool: gridDim.y = t ----------------
__global__ void agg_pool_kernel(const float* __restrict__ hpAll,
                                const float* __restrict__ bias,
                                const float* __restrict__ dinvAll,
                                const int* __restrict__ offsAll,
                                float* __restrict__ gseq)
{
    __shared__ float sacc[128];
    int t = blockIdx.y;
    int lane  = threadIdx.x & 31;
    int wid   = threadIdx.x >> 5;
    int gwarp = blockIdx.x * 8 + wid;
    int nwarps = gridDim.x * 8;

    const float* hp   = hpAll   + (size_t)t * N_NODES * 128;
    const float* dinv = dinvAll + (size_t)t * N_NODES;
    const int*   offs = offsAll + (size_t)t * N_NODES;
    float*       gt   = gseq + t * H_DIM;

    if (threadIdx.x < 128) sacc[threadIdx.x] = 0.0f;
    __syncthreads();

    float4 b = ((const float4*)bias)[lane];
    float4 pool = make_float4(0.f, 0.f, 0.f, 0.f);

    for (int node = gwarp; node < N_NODES; node += nwarps) {
        float4 a = ((const float4*)(hp + (size_t)node * 128))[lane];
        int s = offs[node];
        int e = offs[node + 1];
        for (int j = s; j < e; j++) {
            int src = __ldg(&g_csr[j]);
            float4 v = ((const float4*)(hp + (size_t)src * 128))[lane];
            a.x += v.x; a.y += v.y; a.z += v.z; a.w += v.w;
        }
        float d = dinv[node];
        pool.x += fmaxf(fmaf(d, a.x, b.x), 0.0f);
        pool.y += fmaxf(fmaf(d, a.y, b.y), 0.0f);
        pool.z += fmaxf(fmaf(d, a.z, b.z), 0.0f);
        pool.w += fmaxf(fmaf(d, a.w, b.w), 0.0f);
    }

    atomicAdd(&sacc[lane * 4 + 0], pool.x);
    atomicAdd(&sacc[lane * 4 + 1], pool.y);
    atomicAdd(&sacc[lane * 4 + 2], pool.z);
    atomicAdd(&sacc[lane * 4 + 3], pool.w);
    __syncthreads();
    if (threadIdx.x < 128)
        atomicAdd(&gt[threadIdx.x], sacc[threadIdx.x] * (1.0f / (float)N_NODES));
}

// ---------------- GRU over T steps + head ----------------
__global__ void gru_head_kernel(const float* __restrict__ W_ih,
                                const float* __restrict__ W_hh,
                                const float* __restrict__ b_ih,
                                const float* __restrict__ b_hh,
                                const float* __restrict__ W_head,
                                const float* __restrict__ b_head,
                                float* __restrict__ out)
{
    __shared__ float gbuf[128];
    __shared__ float hbuf[128];
    int j = threadIdx.x;
    hbuf[j] = 0.0f;
    __syncthreads();

    for (int t = 0; t < T_STEPS; t++) {
        gbuf[j] = g_gseq[t * H_DIM + j];
        __syncthreads();
        float gir = b_ih[j], giz = b_ih[128 + j], gin = b_ih[256 + j];
        float ghr = b_hh[j], ghz = b_hh[128 + j], ghn = b_hh[256 + j];
        const float* wi0 = W_ih + (size_t)j * 128;
        const float* wi1 = W_ih + (size_t)(128 + j) * 128;
        const float* wi2 = W_ih + (size_t)(256 + j) * 128;
        const float* wh0 = W_hh + (size_t)j * 128;
        const float* wh1 = W_hh + (size_t)(128 + j) * 128;
        const float* wh2 = W_hh + (size_t)(256 + j) * 128;
        #pragma unroll 4
        for (int k = 0; k < 128; k++) {
            float gk = gbuf[k], hk = hbuf[k];
            gir = fmaf(wi0[k], gk, gir);
            giz = fmaf(wi1[k], gk, giz);
            gin = fmaf(wi2[k], gk, gin);
            ghr = fmaf(wh0[k], hk, ghr);
            ghz = fmaf(wh1[k], hk, ghz);
            ghn = fmaf(wh2[k], hk, ghn);
        }
        float r  = 1.0f / (1.0f + expf(-(gir + ghr)));
        float z  = 1.0f / (1.0f + expf(-(giz + ghz)));
        float nn = tanhf(gin + r * ghn);
        float hn = (1.0f - z) * nn + z * hbuf[j];
        __syncthreads();
        hbuf[j] = hn;
        __syncthreads();
    }

    float o = b_head[j];
    const float* wr = W_head + (size_t)j * 128;
    #pragma unroll 4
    for (int k = 0; k < 128; k++) o = fmaf(wr[k], hbuf[k], o);
    out[j] = o;
}

// ---------------- launch ----------------
extern "C" void kernel_launch(void* const* d_in, const int* in_sizes, int n_in,
                              void* d_out, int out_size)
{
    const float* x_seq  = (const float*)d_in[0];
    const int*   ei_seq = (const int*)  d_in[1];
    const float* W1     = (const float*)d_in[2];
    const float* b1     = (const float*)d_in[3];
    const float* W2     = (const float*)d_in[4];
    const float* b2     = (const float*)d_in[5];
    const float* W_ih   = (const float*)d_in[6];
    const float* W_hh   = (const float*)d_in[7];
    const float* b_ih   = (const float*)d_in[8];
    const float* b_hh   = (const float*)d_in[9];
    const float* W_head = (const float*)d_in[10];
    const float* b_head = (const float*)d_in[11];
    float* out = (float*)d_out;

    float* bufA;   cudaGetSymbolAddress((void**)&bufA, g_bufA);
    float* bufB;   cudaGetSymbolAddress((void**)&bufB, g_bufB);
    float* dinv;   cudaGetSymbolAddress((void**)&dinv, g_dinv);
    int*   offs;   cudaGetSymbolAddress((void**)&offs, g_offsets);
    float* gseq;   cudaGetSymbolAddress((void**)&gseq, g_gseq);

    const int GEB = (T_STEPS * E_EDGES + 255) / 256;     // edge grid
    const int GM  = (TOTAL_ROWS + 127) / 128;            // 4688 gemm blocks
    const int AGX = (N_NODES + 7) / 8;                   // agg blocks per t (warp/node)
    const int APX = 624;                                 // agg_pool blocks per t

    // ---- CSR build (batched over all t) ----
    zero_all_kernel<<<(TOTAL_CNT + 255) / 256, 256>>>();
    count_all_kernel<<<GEB, 256>>>(ei_seq);
    scan1_kernel<<<NB_SCAN, 1024>>>();
    scan2_kernel<<<1, 1024>>>();
    scan3_kernel<<<NB_SCAN, 1024>>>();
    fill_all_kernel<<<GEB, 256>>>(ei_seq);

    // ---- 4 giant batched phases ----
    gemm_scale_kernel<<<GM, 256>>>(x_seq, W1, dinv, bufA, TOTAL_ROWS);
    {
        dim3 g(AGX, T_STEPS);
        agg_kernel<<<g, 256>>>(bufA, b1, dinv, offs, bufB);
    }
    gemm_scale_kernel<<<GM, 256>>>(bufB, W2, dinv, bufA, TOTAL_ROWS);
    {
        dim3 g(APX, T_STEPS);
        agg_pool_kernel<<<g, 256>>>(bufA, b2, dinv, offs, gseq);
    }

    gru_head_kernel<<<1, 128>>>(W_ih, W_hh, b_ih, b_hh, W_head, b_head, out);
}

// round 4
// speedup vs baseline: 2.2580x; 1.2969x over previous
#include <cuda_runtime.h>
#include <cuda_fp16.h>
#include <math.h>

#define T_STEPS 12
#define N_NODES 50000
#define E_EDGES 800000
#define C_DIM   128
#define H_DIM   128

#define TOTAL_CNT  (T_STEPS * N_NODES)            // 600000
#define TOTAL_ROWS (T_STEPS * N_NODES)            // 600000 flat rows
#define NB_SCAN    ((TOTAL_CNT + 1023) / 1024)    // 586

// ---------------- device scratch ----------------
__device__ int    g_counts [TOTAL_CNT];
__device__ int    g_cursor [TOTAL_CNT];
__device__ int    g_offsets[TOTAL_CNT + 1];
__device__ int    g_bsums  [1024];
__device__ int    g_bbase  [1024];
__device__ int    g_csr    [T_STEPS * E_EDGES];        // 9.6M
__device__ float  g_dinv   [TOTAL_CNT];
__device__ __half g_bufA   [TOTAL_ROWS * 128];         // 154 MB
__device__ __half g_bufB   [TOTAL_ROWS * 128];         // 154 MB
__device__ float  g_gseq   [T_STEPS * H_DIM];

// ---------------- helpers ----------------
__device__ __forceinline__ unsigned f2tf32(float f) {
    unsigned r;
    asm("cvt.rna.tf32.f32 %0, %1;" : "=r"(r) : "f"(f));
    return r;
}
__device__ __forceinline__ float4 h4_to_f4(uint2 u) {
    __half2 h0 = *(__half2*)&u.x;
    __half2 h1 = *(__half2*)&u.y;
    float2 f0 = __half22float2(h0);
    float2 f1 = __half22float2(h1);
    return make_float4(f0.x, f0.y, f1.x, f1.y);
}

// ---------------- zero counters / gseq ----------------
__global__ void zero_all_kernel() {
    int i = blockIdx.x * blockDim.x + threadIdx.x;
    if (i < TOTAL_CNT) { g_counts[i] = 0; g_cursor[i] = 0; }
    if (i < T_STEPS * H_DIM) g_gseq[i] = 0.0f;
}

// ---------------- count degrees (all timesteps) ----------------
__global__ void count_all_kernel(const int* __restrict__ ei_seq) {
    int g = blockIdx.x * blockDim.x + threadIdx.x;
    if (g >= T_STEPS * E_EDGES) return;
    int t = g / E_EDGES;
    int e = g - t * E_EDGES;
    int d = ei_seq[(size_t)t * 2 * E_EDGES + E_EDGES + e];
    atomicAdd(&g_counts[t * N_NODES + d], 1);
}

// ---------------- hierarchical scan ----------------
__global__ void scan1_kernel() {
    __shared__ int wt[32];
    int lane = threadIdx.x & 31;
    int wid  = threadIdx.x >> 5;
    int gid  = blockIdx.x * 1024 + threadIdx.x;
    int v = (gid < TOTAL_CNT) ? g_counts[gid] : 0;
    int s = v;
    #pragma unroll
    for (int off = 1; off < 32; off <<= 1) {
        int u = __shfl_up_sync(0xFFFFFFFFu, s, off);
        if (lane >= off) s += u;
    }
    if (lane == 31) wt[wid] = s;
    __syncthreads();
    if (wid == 0) {
        int w = wt[lane];
        int ws = w;
        #pragma unroll
        for (int off = 1; off < 32; off <<= 1) {
            int u = __shfl_up_sync(0xFFFFFFFFu, ws, off);
            if (lane >= off) ws += u;
        }
        wt[lane] = ws - w;
    }
    __syncthreads();
    int excl = wt[wid] + (s - v);
    if (gid < TOTAL_CNT) {
        g_offsets[gid] = excl;
        g_dinv[gid]    = rsqrtf((float)(v + 1));
    }
    if (threadIdx.x == 1023) g_bsums[blockIdx.x] = excl + v;
}

__global__ void scan2_kernel() {
    __shared__ int wt[32];
    int lane = threadIdx.x & 31;
    int wid  = threadIdx.x >> 5;
    int i = threadIdx.x;
    int v = (i < NB_SCAN) ? g_bsums[i] : 0;
    int s = v;
    #pragma unroll
    for (int off = 1; off < 32; off <<= 1) {
        int u = __shfl_up_sync(0xFFFFFFFFu, s, off);
        if (lane >= off) s += u;
    }
    if (lane == 31) wt[wid] = s;
    __syncthreads();
    if (wid == 0) {
        int w = wt[lane];
        int ws = w;
        #pragma unroll
        for (int off = 1; off < 32; off <<= 1) {
            int u = __shfl_up_sync(0xFFFFFFFFu, ws, off);
            if (lane >= off) ws += u;
        }
        wt[lane] = ws - w;
    }
    __syncthreads();
    g_bbase[i] = wt[wid] + (s - v);
}

__global__ void scan3_kernel() {
    int gid = blockIdx.x * 1024 + threadIdx.x;
    if (gid < TOTAL_CNT) g_offsets[gid] += g_bbase[blockIdx.x];
    if (gid == 0) g_offsets[TOTAL_CNT] = T_STEPS * E_EDGES;
}

// ---------------- fill CSR (all timesteps) ----------------
__global__ void fill_all_kernel(const int* __restrict__ ei_seq) {
    int g = blockIdx.x * blockDim.x + threadIdx.x;
    if (g >= T_STEPS * E_EDGES) return;
    int t = g / E_EDGES;
    int e = g - t * E_EDGES;
    const int* base = ei_seq + (size_t)t * 2 * E_EDGES;
    int sv = base[e];
    int dv = base[E_EDGES + e];
    int f  = t * N_NODES + dv;
    int pos = g_offsets[f] + atomicAdd(&g_cursor[f], 1);
    g_csr[pos] = sv;
}

// ---------------- TF32 tensor-core GEMM: Y(half) = diag(dinv) * (A @ W) ----------------
// Block tile 128x128, K=128 in 16 steps of 8. 8 warps, warp tile 32x64.
// mma.sync.m16n8k8 tf32. Smem stride 136 floats -> conflict-free fragment loads.
// A_HALF: A is __half (layer-2 input), else float.
template <bool A_HALF>
__global__ void gemm_tf32_kernel(const void* __restrict__ Ain,
                                 const float* __restrict__ W,
                                 const float* __restrict__ dinv,
                                 __half* __restrict__ Y, int M)
{
    __shared__ unsigned As[8][136];
    __shared__ unsigned Bs[8][136];

    const int tid  = threadIdx.x;         // 0..255
    const int lane = tid & 31;
    const int wid  = tid >> 5;            // 0..7
    const int wm   = wid & 3;             // warp M group (4 x 32 = 128)
    const int wn   = wid >> 2;            // warp N group (2 x 64 = 128)
    const int g    = lane >> 2;           // 0..7
    const int tig  = lane & 3;            // 0..3
    const int row0 = blockIdx.x * 128;

    float acc[2][8][4];
    #pragma unroll
    for (int mi = 0; mi < 2; mi++)
        #pragma unroll
        for (int ni = 0; ni < 8; ni++)
            #pragma unroll
            for (int q = 0; q < 4; q++) acc[mi][ni][q] = 0.0f;

    // staging indices
    const int am = tid >> 1;              // A row within tile (0..127)
    const int ak = (tid & 1) * 4;         // A k offset within 8
    const int bk = tid >> 5;              // B k row (0..7)
    const int bn = (tid & 31) * 4;        // B col (0..124)

    const int  agr     = row0 + am;
    const bool arow_ok = (agr < M);

    const float*  Af = (const float*) Ain;
    const __half* Ah = (const __half*)Ain;

    // prefetch k0 = 0
    float a_pf[4] = {0.f, 0.f, 0.f, 0.f};
    if (arow_ok) {
        if (A_HALF) {
            uint2 u = *(const uint2*)(Ah + (size_t)agr * 128 + ak);
            float4 f = h4_to_f4(u);
            a_pf[0] = f.x; a_pf[1] = f.y; a_pf[2] = f.z; a_pf[3] = f.w;
        } else {
            float4 f = *(const float4*)(Af + (size_t)agr * 128 + ak);
            a_pf[0] = f.x; a_pf[1] = f.y; a_pf[2] = f.z; a_pf[3] = f.w;
        }
    }
    float4 b_pf = *(const float4*)(W + (size_t)bk * 128 + bn);

    for (int k0 = 0; k0 < 128; k0 += 8) {
        // store (converted) tiles
        #pragma unroll
        for (int q = 0; q < 4; q++) As[ak + q][am] = f2tf32(a_pf[q]);
        Bs[bk][bn + 0] = f2tf32(b_pf.x);
        Bs[bk][bn + 1] = f2tf32(b_pf.y);
        Bs[bk][bn + 2] = f2tf32(b_pf.z);
        Bs[bk][bn + 3] = f2tf32(b_pf.w);
        __syncthreads();

        if (k0 + 8 < 128) {
            if (arow_ok) {
                if (A_HALF) {
                    uint2 u = *(const uint2*)(Ah + (size_t)agr * 128 + k0 + 8 + ak);
                    float4 f = h4_to_f4(u);
                    a_pf[0] = f.x; a_pf[1] = f.y; a_pf[2] = f.z; a_pf[3] = f.w;
                } else {
                    float4 f = *(const float4*)(Af + (size_t)agr * 128 + k0 + 8 + ak);
                    a_pf[0] = f.x; a_pf[1] = f.y; a_pf[2] = f.z; a_pf[3] = f.w;
                }
            }
            b_pf = *(const float4*)(W + (size_t)(k0 + 8 + bk) * 128 + bn);
        }

        // fragments
        unsigned afr[2][4];
        #pragma unroll
        for (int mi = 0; mi < 2; mi++) {
            int rm = wm * 32 + mi * 16;
            afr[mi][0] = As[tig    ][rm + g    ];
            afr[mi][1] = As[tig    ][rm + g + 8];
            afr[mi][2] = As[tig + 4][rm + g    ];
            afr[mi][3] = As[tig + 4][rm + g + 8];
        }
        unsigned bfr[8][2];
        #pragma unroll
        for (int ni = 0; ni < 8; ni++) {
            int cb = wn * 64 + ni * 8 + g;
            bfr[ni][0] = Bs[tig    ][cb];
            bfr[ni][1] = Bs[tig + 4][cb];
        }

        #pragma unroll
        for (int mi = 0; mi < 2; mi++)
            #pragma unroll
            for (int ni = 0; ni < 8; ni++) {
                asm volatile(
                    "mma.sync.aligned.m16n8k8.row.col.f32.tf32.tf32.f32 "
                    "{%0,%1,%2,%3},{%4,%5,%6,%7},{%8,%9},{%0,%1,%2,%3};"
                    : "+f"(acc[mi][ni][0]), "+f"(acc[mi][ni][1]),
                      "+f"(acc[mi][ni][2]), "+f"(acc[mi][ni][3])
                    : "r"(afr[mi][0]), "r"(afr[mi][1]),
                      "r"(afr[mi][2]), "r"(afr[mi][3]),
                      "r"(bfr[ni][0]), "r"(bfr[ni][1]));
            }
        __syncthreads();
    }

    // epilogue: dinv scale + fp16 store
    #pragma unroll
    for (int mi = 0; mi < 2; mi++) {
        #pragma unroll
        for (int hh = 0; hh < 2; hh++) {
            int r = row0 + wm * 32 + mi * 16 + g + hh * 8;
            if (r < M) {
                float d = dinv[r];
                #pragma unroll
                for (int ni = 0; ni < 8; ni++) {
                    int c = wn * 64 + ni * 8 + 2 * tig;
                    __half2 h = __floats2half2_rn(d * acc[mi][ni][hh * 2 + 0],
                                                  d * acc[mi][ni][hh * 2 + 1]);
                    *(__half2*)(Y + (size_t)r * 128 + c) = h;
                }
            }
        }
    }
}

// ---------------- batched layer-1 aggregation (half in/out) ----------------
__global__ void agg_kernel(const __half* __restrict__ hpAll,
                           const float* __restrict__ bias,
                           const float* __restrict__ dinvAll,
                           const int* __restrict__ offsAll,
                           __half* __restrict__ outAll)
{
    int t = blockIdx.y;
    int node = (blockIdx.x * blockDim.x + threadIdx.x) >> 5;
    int lane = threadIdx.x & 31;
    if (node >= N_NODES) return;

    const __half* hp   = hpAll   + (size_t)t * N_NODES * 128;
    const float*  dinv = dinvAll + (size_t)t * N_NODES;
    const int*    offs = offsAll + (size_t)t * N_NODES;
    __half*       out  = outAll  + (size_t)t * N_NODES * 128;

    float4 a = h4_to_f4(((const uint2*)(hp + (size_t)node * 128))[lane]);  // self loop
    int s = offs[node];
    int e = offs[node + 1];
    for (int j = s; j < e; j++) {
        int src = __ldg(&g_csr[j]);
        float4 v = h4_to_f4(((const uint2*)(hp + (size_t)src * 128))[lane]);
        a.x += v.x; a.y += v.y; a.z += v.z; a.w += v.w;
    }
    float  d = dinv[node];
    float4 b = ((const float4*)bias)[lane];
    float rx = fmaxf(fmaf(d, a.x, b.x), 0.0f);
    float ry = fmaxf(fmaf(d, a.y, b.y), 0.0f);
    float rz = fmaxf(fmaf(d, a.z, b.z), 0.0f);
    float rw = fmaxf(fmaf(d, a.w, b.w), 0.0f);
    uint2 o;
    __half2 h0 = __floats2half2_rn(rx, ry);
    __half2 h1 = __floats2half2_rn(rz, rw);
    o.x = *(unsigned*)&h0;
    o.y = *(unsigned*)&h1;
    ((uint2*)(out + (size_t)node * 128))[lane] = o;
}

// ---------------- batched layer-2 agg + mean pool (half in) ----------------
__global__ void agg_pool_kernel(const __half* __restrict__ hpAll,
                                const float* __restrict__ bias,
                                const float* __restrict__ dinvAll,
                                const int* __restrict__ offsAll,
                                float* __restrict__ gseq)
{
    __shared__ float sacc[128];
    int t = blockIdx.y;
    int lane  = threadIdx.x & 31;
    int wid   = threadIdx.x >> 5;
    int gwarp = blockIdx.x * 8 + wid;
    int nwarps = gridDim.x * 8;

    const __half* hp   = hpAll   + (size_t)t * N_NODES * 128;
    const float*  dinv = dinvAll + (size_t)t * N_NODES;
    const int*    offs = offsAll + (size_t)t * N_NODES;
    float*        gt   = gseq + t * H_DIM;

    if (threadIdx.x < 128) sacc[threadIdx.x] = 0.0f;
    __syncthreads();

    float4 b = ((const float4*)bias)[lane];
    float4 pool = make_float4(0.f, 0.f, 0.f, 0.f);

    for (int node = gwarp; node < N_NODES; node += nwarps) {
        float4 a = h4_to_f4(((const uint2*)(hp + (size_t)node * 128))[lane]);
        int s = offs[node];
        int e = offs[node + 1];
        for (int j = s; j < e; j++) {
            int src = __ldg(&g_csr[j]);
            float4 v = h4_to_f4(((const uint2*)(hp + (size_t)src * 128))[lane]);
            a.x += v.x; a.y += v.y; a.z += v.z; a.w += v.w;
        }
        float d = dinv[node];
        pool.x += fmaxf(fmaf(d, a.x, b.x), 0.0f);
        pool.y += fmaxf(fmaf(d, a.y, b.y), 0.0f);
        pool.z += fmaxf(fmaf(d, a.z, b.z), 0.0f);
        pool.w += fmaxf(fmaf(d, a.w, b.w), 0.0f);
    }

    atomicAdd(&sacc[lane * 4 + 0], pool.x);
    atomicAdd(&sacc[lane * 4 + 1], pool.y);
    atomicAdd(&sacc[lane * 4 + 2], pool.z);
    atomicAdd(&sacc[lane * 4 + 3], pool.w);
    __syncthreads();
    if (threadIdx.x < 128)
        atomicAdd(&gt[threadIdx.x], sacc[threadIdx.x] * (1.0f / (float)N_NODES));
}

// ---------------- GRU over T steps + head ----------------
__global__ void gru_head_kernel(const float* __restrict__ W_ih,
                                const float* __restrict__ W_hh,
                                const float* __restrict__ b_ih,
                                const float* __restrict__ b_hh,
                                const float* __restrict__ W_head,
                                const float* __restrict__ b_head,
                                float* __restrict__ out)
{
    __shared__ float gbuf[128];
    __shared__ float hbuf[128];
    int j = threadIdx.x;
    hbuf[j] = 0.0f;
    __syncthreads();

    for (int t = 0; t < T_STEPS; t++) {
        gbuf[j] = g_gseq[t * H_DIM + j];
        __syncthreads();
        float gir = b_ih[j], giz = b_ih[128 + j], gin = b_ih[256 + j];
        float ghr = b_hh[j], ghz = b_hh[128 + j], ghn = b_hh[256 + j];
        const float* wi0 = W_ih + (size_t)j * 128;
        const float* wi1 = W_ih + (size_t)(128 + j) * 128;
        const float* wi2 = W_ih + (size_t)(256 + j) * 128;
        const float* wh0 = W_hh + (size_t)j * 128;
        const float* wh1 = W_hh + (size_t)(128 + j) * 128;
        const float* wh2 = W_hh + (size_t)(256 + j) * 128;
        #pragma unroll 4
        for (int k = 0; k < 128; k++) {
            float gk = gbuf[k], hk = hbuf[k];
            gir = fmaf(wi0[k], gk, gir);
            giz = fmaf(wi1[k], gk, giz);
            gin = fmaf(wi2[k], gk, gin);
            ghr = fmaf(wh0[k], hk, ghr);
            ghz = fmaf(wh1[k], hk, ghz);
            ghn = fmaf(wh2[k], hk, ghn);
        }
        float r  = 1.0f / (1.0f + expf(-(gir + ghr)));
        float z  = 1.0f / (1.0f + expf(-(giz + ghz)));
        float nn = tanhf(gin + r * ghn);
        float hn = (1.0f - z) * nn + z * hbuf[j];
        __syncthreads();
        hbuf[j] = hn;
        __syncthreads();
    }

    float o = b_head[j];
    const float* wr = W_head + (size_t)j * 128;
    #pragma unroll 4
    for (int k = 0; k < 128; k++) o = fmaf(wr[k], hbuf[k], o);
    out[j] = o;
}

// ---------------- launch ----------------
extern "C" void kernel_launch(void* const* d_in, const int* in_sizes, int n_in,
                              void* d_out, int out_size)
{
    const float* x_seq  = (const float*)d_in[0];
    const int*   ei_seq = (const int*)  d_in[1];
    const float* W1     = (const float*)d_in[2];
    const float* b1     = (const float*)d_in[3];
    const float* W2     = (const float*)d_in[4];
    const float* b2     = (const float*)d_in[5];
    const float* W_ih   = (const float*)d_in[6];
    const float* W_hh   = (const float*)d_in[7];
    const float* b_ih   = (const float*)d_in[8];
    const float* b_hh   = (const float*)d_in[9];
    const float* W_head = (const float*)d_in[10];
    const float* b_head = (const float*)d_in[11];
    float* out = (float*)d_out;

    __half* bufA;  cudaGetSymbolAddress((void**)&bufA, g_bufA);
    __half* bufB;  cudaGetSymbolAddress((void**)&bufB, g_bufB);
    float*  dinv;  cudaGetSymbolAddress((void**)&dinv, g_dinv);
    int*    offs;  cudaGetSymbolAddress((void**)&offs, g_offsets);
    float*  gseq;  cudaGetSymbolAddress((void**)&gseq, g_gseq);

    const int GEB = (T_STEPS * E_EDGES + 255) / 256;     // edge grid
    const int GM  = (TOTAL_ROWS + 127) / 128;            // 4688 gemm blocks
    const int AGX = (N_NODES + 7) / 8;                   // agg blocks per t
    const int APX = 624;                                 // agg_pool blocks per t

    // ---- CSR build + phases (gemm1 placed early so ncu samples it) ----
    zero_all_kernel<<<(TOTAL_CNT + 255) / 256, 256>>>();         // #0
    count_all_kernel<<<GEB, 256>>>(ei_seq);                      // #1
    scan1_kernel<<<NB_SCAN, 1024>>>();                           // #2 (writes dinv)
    gemm_tf32_kernel<false><<<GM, 256>>>(x_seq, W1, dinv, bufA, TOTAL_ROWS);  // #3
    scan2_kernel<<<1, 1024>>>();                                 // #4
    scan3_kernel<<<NB_SCAN, 1024>>>();                           // #5
    fill_all_kernel<<<GEB, 256>>>(ei_seq);                       // #6

    {
        dim3 g(AGX, T_STEPS);
        agg_kernel<<<g, 256>>>(bufA, b1, dinv, offs, bufB);      // #7
    }
    gemm_tf32_kernel<true><<<GM, 256>>>(bufB, W2, dinv, bufA, TOTAL_ROWS);    // #8
    {
        dim3 g(APX, T_STEPS);
        agg_pool_kernel<<<g, 256>>>(bufA, b2, dinv, offs, gseq); // #9
    }

    gru_head_kernel<<<1, 128>>>(W_ih, W_hh, b_ih, b_hh, W_head, b_head, out); // #10
}

// round 5
// speedup vs baseline: 2.3579x; 1.0442x over previous
#include <cuda_runtime.h>
#include <cuda_fp16.h>
#include <math.h>

#define T_STEPS 12
#define N_NODES 50000
#define E_EDGES 800000
#define C_DIM   128
#define H_DIM   128

#define TOTAL_CNT  (T_STEPS * N_NODES)            // 600000
#define TOTAL_ROWS (T_STEPS * N_NODES)            // 600000 flat rows
#define NB_SCAN    ((TOTAL_CNT + 1023) / 1024)    // 586

// ---------------- device scratch ----------------
__device__ int    g_counts [TOTAL_CNT];
__device__ int    g_cursor [TOTAL_CNT];
__device__ int    g_offsets[TOTAL_CNT + 1];
__device__ int    g_bsums  [1024];
__device__ int    g_bbase  [1024];
__device__ int    g_csr    [T_STEPS * E_EDGES];        // 9.6M
__device__ float  g_dinv   [TOTAL_CNT];
__device__ __half g_bufA   [TOTAL_ROWS * 128];         // 154 MB
__device__ __half g_bufB   [TOTAL_ROWS * 128];         // 154 MB
__device__ float  g_gseq   [T_STEPS * H_DIM];

// ---------------- helpers ----------------
__device__ __forceinline__ unsigned pack_h2(float a, float b) {
    __half2 h = __floats2half2_rn(a, b);
    return *(unsigned*)&h;
}
__device__ __forceinline__ float4 h4_to_f4(uint2 u) {
    __half2 h0 = *(__half2*)&u.x;
    __half2 h1 = *(__half2*)&u.y;
    float2 f0 = __half22float2(h0);
    float2 f1 = __half22float2(h1);
    return make_float4(f0.x, f0.y, f1.x, f1.y);
}

// ---------------- zero counters / gseq ----------------
__global__ void zero_all_kernel() {
    int i = blockIdx.x * blockDim.x + threadIdx.x;
    if (i < TOTAL_CNT) { g_counts[i] = 0; g_cursor[i] = 0; }
    if (i < T_STEPS * H_DIM) g_gseq[i] = 0.0f;
}

// ---------------- count degrees (all timesteps) ----------------
__global__ void count_all_kernel(const int* __restrict__ ei_seq) {
    int g = blockIdx.x * blockDim.x + threadIdx.x;
    if (g >= T_STEPS * E_EDGES) return;
    int t = g / E_EDGES;
    int e = g - t * E_EDGES;
    int d = ei_seq[(size_t)t * 2 * E_EDGES + E_EDGES + e];
    atomicAdd(&g_counts[t * N_NODES + d], 1);
}

// ---------------- hierarchical scan ----------------
__global__ void scan1_kernel() {
    __shared__ int wt[32];
    int lane = threadIdx.x & 31;
    int wid  = threadIdx.x >> 5;
    int gid  = blockIdx.x * 1024 + threadIdx.x;
    int v = (gid < TOTAL_CNT) ? g_counts[gid] : 0;
    int s = v;
    #pragma unroll
    for (int off = 1; off < 32; off <<= 1) {
        int u = __shfl_up_sync(0xFFFFFFFFu, s, off);
        if (lane >= off) s += u;
    }
    if (lane == 31) wt[wid] = s;
    __syncthreads();
    if (wid == 0) {
        int w = wt[lane];
        int ws = w;
        #pragma unroll
        for (int off = 1; off < 32; off <<= 1) {
            int u = __shfl_up_sync(0xFFFFFFFFu, ws, off);
            if (lane >= off) ws += u;
        }
        wt[lane] = ws - w;
    }
    __syncthreads();
    int excl = wt[wid] + (s - v);
    if (gid < TOTAL_CNT) {
        g_offsets[gid] = excl;
        g_dinv[gid]    = rsqrtf((float)(v + 1));
    }
    if (threadIdx.x == 1023) g_bsums[blockIdx.x] = excl + v;
}

__global__ void scan2_kernel() {
    __shared__ int wt[32];
    int lane = threadIdx.x & 31;
    int wid  = threadIdx.x >> 5;
    int i = threadIdx.x;
    int v = (i < NB_SCAN) ? g_bsums[i] : 0;
    int s = v;
    #pragma unroll
    for (int off = 1; off < 32; off <<= 1) {
        int u = __shfl_up_sync(0xFFFFFFFFu, s, off);
        if (lane >= off) s += u;
    }
    if (lane == 31) wt[wid] = s;
    __syncthreads();
    if (wid == 0) {
        int w = wt[lane];
        int ws = w;
        #pragma unroll
        for (int off = 1; off < 32; off <<= 1) {
            int u = __shfl_up_sync(0xFFFFFFFFu, ws, off);
            if (lane >= off) ws += u;
        }
        wt[lane] = ws - w;
    }
    __syncthreads();
    g_bbase[i] = wt[wid] + (s - v);
}

__global__ void scan3_kernel() {
    int gid = blockIdx.x * 1024 + threadIdx.x;
    if (gid < TOTAL_CNT) g_offsets[gid] += g_bbase[blockIdx.x];
    if (gid == 0) g_offsets[TOTAL_CNT] = T_STEPS * E_EDGES;
}

// ---------------- fill CSR (all timesteps) ----------------
__global__ void fill_all_kernel(const int* __restrict__ ei_seq) {
    int g = blockIdx.x * blockDim.x + threadIdx.x;
    if (g >= T_STEPS * E_EDGES) return;
    int t = g / E_EDGES;
    int e = g - t * E_EDGES;
    const int* base = ei_seq + (size_t)t * 2 * E_EDGES;
    int sv = base[e];
    int dv = base[E_EDGES + e];
    int f  = t * N_NODES + dv;
    int pos = g_offsets[f] + atomicAdd(&g_cursor[f], 1);
    g_csr[pos] = sv;
}

// ---------------- fp16 tensor-core GEMM: Y(half) = diag(dinv) * (A @ W) ----------------
// Block tile 128x128, K=128 in 8 steps of 16. 8 warps, warp tile 32x64.
// mma.sync.m16n8k16.f16 with fp32 accumulate. Smem cells = half2 (k,k+1) pairs;
// fragment indexing identical to the tf32 m16n8k8 layout, conflict-free (stride 136).
template <bool A_HALF>
__global__ void gemm_f16_kernel(const void* __restrict__ Ain,
                                const float* __restrict__ W,
                                const float* __restrict__ dinv,
                                __half* __restrict__ Y, int M)
{
    __shared__ unsigned As[8][136];   // [k_pair][row]
    __shared__ unsigned Bs[8][136];   // [k_pair][col]

    const int tid  = threadIdx.x;         // 0..255
    const int lane = tid & 31;
    const int wid  = tid >> 5;            // 0..7
    const int wm   = wid & 3;             // warp M group (4 x 32 = 128)
    const int wn   = wid >> 2;            // warp N group (2 x 64 = 128)
    const int g    = lane >> 2;           // 0..7
    const int tig  = lane & 3;            // 0..3
    const int row0 = blockIdx.x * 128;

    float acc[2][8][4];
    #pragma unroll
    for (int mi = 0; mi < 2; mi++)
        #pragma unroll
        for (int ni = 0; ni < 8; ni++)
            #pragma unroll
            for (int q = 0; q < 4; q++) acc[mi][ni][q] = 0.0f;

    // A staging: am = row (0..127), akp = k-pair offset 0 or 4 (k offset 0 or 8)
    const int am  = tid >> 1;
    const int akp = (tid & 1) * 4;
    // B staging: p = k-pair row (0..7), n0 = col (0..124)
    const int bp  = tid >> 5;
    const int bn  = (tid & 31) * 4;

    const int  agr     = row0 + am;
    const bool arow_ok = (agr < M);

    const float*  Af = (const float*) Ain;
    const __half* Ah = (const __half*)Ain;

    // ---- prefetch k0 = 0 ----
    unsigned a_st[4] = {0u, 0u, 0u, 0u};
    if (arow_ok) {
        if (A_HALF) {
            uint4 u = *(const uint4*)(Ah + (size_t)agr * 128 + akp * 2);
            a_st[0] = u.x; a_st[1] = u.y; a_st[2] = u.z; a_st[3] = u.w;
        } else {
            float4 f0 = *(const float4*)(Af + (size_t)agr * 128 + akp * 2);
            float4 f1 = *(const float4*)(Af + (size_t)agr * 128 + akp * 2 + 4);
            a_st[0] = pack_h2(f0.x, f0.y); a_st[1] = pack_h2(f0.z, f0.w);
            a_st[2] = pack_h2(f1.x, f1.y); a_st[3] = pack_h2(f1.z, f1.w);
        }
    }
    unsigned b_st[4];
    {
        float4 f0 = *(const float4*)(W + (size_t)(2 * bp)     * 128 + bn);
        float4 f1 = *(const float4*)(W + (size_t)(2 * bp + 1) * 128 + bn);
        b_st[0] = pack_h2(f0.x, f1.x); b_st[1] = pack_h2(f0.y, f1.y);
        b_st[2] = pack_h2(f0.z, f1.z); b_st[3] = pack_h2(f0.w, f1.w);
    }

    for (int k0 = 0; k0 < 128; k0 += 16) {
        // commit staged tiles
        #pragma unroll
        for (int q = 0; q < 4; q++) As[akp + q][am] = a_st[q];
        #pragma unroll
        for (int q = 0; q < 4; q++) Bs[bp][bn + q] = b_st[q];
        __syncthreads();

        // prefetch next
        if (k0 + 16 < 128) {
            if (arow_ok) {
                if (A_HALF) {
                    uint4 u = *(const uint4*)(Ah + (size_t)agr * 128 + k0 + 16 + akp * 2);
                    a_st[0] = u.x; a_st[1] = u.y; a_st[2] = u.z; a_st[3] = u.w;
                } else {
                    float4 f0 = *(const float4*)(Af + (size_t)agr * 128 + k0 + 16 + akp * 2);
                    float4 f1 = *(const float4*)(Af + (size_t)agr * 128 + k0 + 16 + akp * 2 + 4);
                    a_st[0] = pack_h2(f0.x, f0.y); a_st[1] = pack_h2(f0.z, f0.w);
                    a_st[2] = pack_h2(f1.x, f1.y); a_st[3] = pack_h2(f1.z, f1.w);
                }
            }
            float4 f0 = *(const float4*)(W + (size_t)(k0 + 16 + 2 * bp)     * 128 + bn);
            float4 f1 = *(const float4*)(W + (size_t)(k0 + 16 + 2 * bp + 1) * 128 + bn);
            b_st[0] = pack_h2(f0.x, f1.x); b_st[1] = pack_h2(f0.y, f1.y);
            b_st[2] = pack_h2(f0.z, f1.z); b_st[3] = pack_h2(f0.w, f1.w);
        }

        // fragments (identical indexing to tf32 m16n8k8 layout)
        unsigned afr[2][4];
        #pragma unroll
        for (int mi = 0; mi < 2; mi++) {
            int rm = wm * 32 + mi * 16;
            afr[mi][0] = As[tig    ][rm + g    ];
            afr[mi][1] = As[tig    ][rm + g + 8];
            afr[mi][2] = As[tig + 4][rm + g    ];
            afr[mi][3] = As[tig + 4][rm + g + 8];
        }
        unsigned bfr[8][2];
        #pragma unroll
        for (int ni = 0; ni < 8; ni++) {
            int cb = wn * 64 + ni * 8 + g;
            bfr[ni][0] = Bs[tig    ][cb];
            bfr[ni][1] = Bs[tig + 4][cb];
        }

        #pragma unroll
        for (int mi = 0; mi < 2; mi++)
            #pragma unroll
            for (int ni = 0; ni < 8; ni++) {
                asm volatile(
                    "mma.sync.aligned.m16n8k16.row.col.f32.f16.f16.f32 "
                    "{%0,%1,%2,%3},{%4,%5,%6,%7},{%8,%9},{%0,%1,%2,%3};"
                    : "+f"(acc[mi][ni][0]), "+f"(acc[mi][ni][1]),
                      "+f"(acc[mi][ni][2]), "+f"(acc[mi][ni][3])
                    : "r"(afr[mi][0]), "r"(afr[mi][1]),
                      "r"(afr[mi][2]), "r"(afr[mi][3]),
                      "r"(bfr[ni][0]), "r"(bfr[ni][1]));
            }
        __syncthreads();
    }

    // epilogue: dinv scale + fp16 store
    #pragma unroll
    for (int mi = 0; mi < 2; mi++) {
        #pragma unroll
        for (int hh = 0; hh < 2; hh++) {
            int r = row0 + wm * 32 + mi * 16 + g + hh * 8;
            if (r < M) {
                float d = dinv[r];
                #pragma unroll
                for (int ni = 0; ni < 8; ni++) {
                    int c = wn * 64 + ni * 8 + 2 * tig;
                    __half2 h = __floats2half2_rn(d * acc[mi][ni][hh * 2 + 0],
                                                  d * acc[mi][ni][hh * 2 + 1]);
                    *(__half2*)(Y + (size_t)r * 128 + c) = h;
                }
            }
        }
    }
}

// ---------------- batched layer-1 aggregation (half in/out), 4x unrolled ----------------
__global__ void agg_kernel(const __half* __restrict__ hpAll,
                           const float* __restrict__ bias,
                           const float* __restrict__ dinvAll,
                           const int* __restrict__ offsAll,
                           __half* __restrict__ outAll)
{
    int t = blockIdx.y;
    int node = (blockIdx.x * blockDim.x + threadIdx.x) >> 5;
    int lane = threadIdx.x & 31;
    if (node >= N_NODES) return;

    const __half* hp   = hpAll   + (size_t)t * N_NODES * 128;
    const float*  dinv = dinvAll + (size_t)t * N_NODES;
    const int*    offs = offsAll + (size_t)t * N_NODES;
    __half*       out  = outAll  + (size_t)t * N_NODES * 128;

    float4 a = h4_to_f4(((const uint2*)(hp + (size_t)node * 128))[lane]);  // self loop
    int s = offs[node];
    int e = offs[node + 1];
    int j = s;
    for (; j + 3 < e; j += 4) {
        int s0 = __ldg(&g_csr[j]);
        int s1 = __ldg(&g_csr[j + 1]);
        int s2 = __ldg(&g_csr[j + 2]);
        int s3 = __ldg(&g_csr[j + 3]);
        uint2 u0 = ((const uint2*)(hp + (size_t)s0 * 128))[lane];
        uint2 u1 = ((const uint2*)(hp + (size_t)s1 * 128))[lane];
        uint2 u2 = ((const uint2*)(hp + (size_t)s2 * 128))[lane];
        uint2 u3 = ((const uint2*)(hp + (size_t)s3 * 128))[lane];
        float4 v0 = h4_to_f4(u0), v1 = h4_to_f4(u1);
        float4 v2 = h4_to_f4(u2), v3 = h4_to_f4(u3);
        a.x += (v0.x + v1.x) + (v2.x + v3.x);
        a.y += (v0.y + v1.y) + (v2.y + v3.y);
        a.z += (v0.z + v1.z) + (v2.z + v3.z);
        a.w += (v0.w + v1.w) + (v2.w + v3.w);
    }
    for (; j < e; j++) {
        int src = __ldg(&g_csr[j]);
        float4 v = h4_to_f4(((const uint2*)(hp + (size_t)src * 128))[lane]);
        a.x += v.x; a.y += v.y; a.z += v.z; a.w += v.w;
    }
    float  d = dinv[node];
    float4 b = ((const float4*)bias)[lane];
    uint2 o;
    o.x = pack_h2(fmaxf(fmaf(d, a.x, b.x), 0.0f), fmaxf(fmaf(d, a.y, b.y), 0.0f));
    o.y = pack_h2(fmaxf(fmaf(d, a.z, b.z), 0.0f), fmaxf(fmaf(d, a.w, b.w), 0.0f));
    ((uint2*)(out + (size_t)node * 128))[lane] = o;
}

// ---------------- batched layer-2 agg + mean pool (half in), 4x unrolled ----------------
__global__ void agg_pool_kernel(const __half* __restrict__ hpAll,
                                const float* __restrict__ bias,
                                const float* __restrict__ dinvAll,
                                const int* __restrict__ offsAll,
                                float* __restrict__ gseq)
{
    __shared__ float sacc[128];
    int t = blockIdx.y;
    int lane  = threadIdx.x & 31;
    int wid   = threadIdx.x >> 5;
    int gwarp = blockIdx.x * 8 + wid;
    int nwarps = gridDim.x * 8;

    const __half* hp   = hpAll   + (size_t)t * N_NODES * 128;
    const float*  dinv = dinvAll + (size_t)t * N_NODES;
    const int*    offs = offsAll + (size_t)t * N_NODES;
    float*        gt   = gseq + t * H_DIM;

    if (threadIdx.x < 128) sacc[threadIdx.x] = 0.0f;
    __syncthreads();

    float4 b = ((const float4*)bias)[lane];
    float4 pool = make_float4(0.f, 0.f, 0.f, 0.f);

    for (int node = gwarp; node < N_NODES; node += nwarps) {
        float4 a = h4_to_f4(((const uint2*)(hp + (size_t)node * 128))[lane]);
        int s = offs[node];
        int e = offs[node + 1];
        int j = s;
        for (; j + 3 < e; j += 4) {
            int s0 = __ldg(&g_csr[j]);
            int s1 = __ldg(&g_csr[j + 1]);
            int s2 = __ldg(&g_csr[j + 2]);
            int s3 = __ldg(&g_csr[j + 3]);
            uint2 u0 = ((const uint2*)(hp + (size_t)s0 * 128))[lane];
            uint2 u1 = ((const uint2*)(hp + (size_t)s1 * 128))[lane];
            uint2 u2 = ((const uint2*)(hp + (size_t)s2 * 128))[lane];
            uint2 u3 = ((const uint2*)(hp + (size_t)s3 * 128))[lane];
            float4 v0 = h4_to_f4(u0), v1 = h4_to_f4(u1);
            float4 v2 = h4_to_f4(u2), v3 = h4_to_f4(u3);
            a.x += (v0.x + v1.x) + (v2.x + v3.x);
            a.y += (v0.y + v1.y) + (v2.y + v3.y);
            a.z += (v0.z + v1.z) + (v2.z + v3.z);
            a.w += (v0.w + v1.w) + (v2.w + v3.w);
        }
        for (; j < e; j++) {
            int src = __ldg(&g_csr[j]);
            float4 v = h4_to_f4(((const uint2*)(hp + (size_t)src * 128))[lane]);
            a.x += v.x; a.y += v.y; a.z += v.z; a.w += v.w;
        }
        float d = dinv[node];
        pool.x += fmaxf(fmaf(d, a.x, b.x), 0.0f);
        pool.y += fmaxf(fmaf(d, a.y, b.y), 0.0f);
        pool.z += fmaxf(fmaf(d, a.z, b.z), 0.0f);
        pool.w += fmaxf(fmaf(d, a.w, b.w), 0.0f);
    }

    atomicAdd(&sacc[lane * 4 + 0], pool.x);
    atomicAdd(&sacc[lane * 4 + 1], pool.y);
    atomicAdd(&sacc[lane * 4 + 2], pool.z);
    atomicAdd(&sacc[lane * 4 + 3], pool.w);
    __syncthreads();
    if (threadIdx.x < 128)
        atomicAdd(&gt[threadIdx.x], sacc[threadIdx.x] * (1.0f / (float)N_NODES));
}

// ---------------- GRU over T steps + head ----------------
__global__ void gru_head_kernel(const float* __restrict__ W_ih,
                                const float* __restrict__ W_hh,
                                const float* __restrict__ b_ih,
                                const float* __restrict__ b_hh,
                                const float* __restrict__ W_head,
                                const float* __restrict__ b_head,
                                float* __restrict__ out)
{
    __shared__ float gbuf[128];
    __shared__ float hbuf[128];
    int j = threadIdx.x;
    hbuf[j] = 0.0f;
    __syncthreads();

    for (int t = 0; t < T_STEPS; t++) {
        gbuf[j] = g_gseq[t * H_DIM + j];
        __syncthreads();
        float gir = b_ih[j], giz = b_ih[128 + j], gin = b_ih[256 + j];
        float ghr = b_hh[j], ghz = b_hh[128 + j], ghn = b_hh[256 + j];
        const float* wi0 = W_ih + (size_t)j * 128;
        const float* wi1 = W_ih + (size_t)(128 + j) * 128;
        const float* wi2 = W_ih + (size_t)(256 + j) * 128;
        const float* wh0 = W_hh + (size_t)j * 128;
        const float* wh1 = W_hh + (size_t)(128 + j) * 128;
        const float* wh2 = W_hh + (size_t)(256 + j) * 128;
        #pragma unroll 4
        for (int k = 0; k < 128; k++) {
            float gk = gbuf[k], hk = hbuf[k];
            gir = fmaf(wi0[k], gk, gir);
            giz = fmaf(wi1[k], gk, giz);
            gin = fmaf(wi2[k], gk, gin);
            ghr = fmaf(wh0[k], hk, ghr);
            ghz = fmaf(wh1[k], hk, ghz);
            ghn = fmaf(wh2[k], hk, ghn);
        }
        float r  = 1.0f / (1.0f + expf(-(gir + ghr)));
        float z  = 1.0f / (1.0f + expf(-(giz + ghz)));
        float nn = tanhf(gin + r * ghn);
        float hn = (1.0f - z) * nn + z * hbuf[j];
        __syncthreads();
        hbuf[j] = hn;
        __syncthreads();
    }

    float o = b_head[j];
    const float* wr = W_head + (size_t)j * 128;
    #pragma unroll 4
    for (int k = 0; k < 128; k++) o = fmaf(wr[k], hbuf[k], o);
    out[j] = o;
}

// ---------------- launch ----------------
extern "C" void kernel_launch(void* const* d_in, const int* in_sizes, int n_in,
                              void* d_out, int out_size)
{
    const float* x_seq  = (const float*)d_in[0];
    const int*   ei_seq = (const int*)  d_in[1];
    const float* W1     = (const float*)d_in[2];
    const float* b1     = (const float*)d_in[3];
    const float* W2     = (const float*)d_in[4];
    const float* b2     = (const float*)d_in[5];
    const float* W_ih   = (const float*)d_in[6];
    const float* W_hh   = (const float*)d_in[7];
    const float* b_ih   = (const float*)d_in[8];
    const float* b_hh   = (const float*)d_in[9];
    const float* W_head = (const float*)d_in[10];
    const float* b_head = (const float*)d_in[11];
    float* out = (float*)d_out;

    __half* bufA;  cudaGetSymbolAddress((void**)&bufA, g_bufA);
    __half* bufB;  cudaGetSymbolAddress((void**)&bufB, g_bufB);
    float*  dinv;  cudaGetSymbolAddress((void**)&dinv, g_dinv);
    int*    offs;  cudaGetSymbolAddress((void**)&offs, g_offsets);
    float*  gseq;  cudaGetSymbolAddress((void**)&gseq, g_gseq);

    const int GEB = (T_STEPS * E_EDGES + 255) / 256;     // edge grid
    const int GM  = (TOTAL_ROWS + 127) / 128;            // 4688 gemm blocks
    const int AGX = (N_NODES + 7) / 8;                   // agg blocks per t
    const int APX = 624;                                 // agg_pool blocks per t

    // ---- CSR build + phases (gemm1 at launch #3 so ncu samples it) ----
    zero_all_kernel<<<(TOTAL_CNT + 255) / 256, 256>>>();         // #0
    count_all_kernel<<<GEB, 256>>>(ei_seq);                      // #1
    scan1_kernel<<<NB_SCAN, 1024>>>();                           // #2 (writes dinv)
    gemm_f16_kernel<false><<<GM, 256>>>(x_seq, W1, dinv, bufA, TOTAL_ROWS);   // #3
    scan2_kernel<<<1, 1024>>>();                                 // #4
    scan3_kernel<<<NB_SCAN, 1024>>>();                           // #5
    fill_all_kernel<<<GEB, 256>>>(ei_seq);                       // #6

    {
        dim3 g(AGX, T_STEPS);
        agg_kernel<<<g, 256>>>(bufA, b1, dinv, offs, bufB);      // #7
    }
    gemm_f16_kernel<true><<<GM, 256>>>(bufB, W2, dinv, bufA, TOTAL_ROWS);     // #8
    {
        dim3 g(APX, T_STEPS);
        agg_pool_kernel<<<g, 256>>>(bufA, b2, dinv, offs, gseq); // #9
    }

    gru_head_kernel<<<1, 128>>>(W_ih, W_hh, b_ih, b_hh, W_head, b_head, out); // #10
}

// round 6
// speedup vs baseline: 2.4927x; 1.0572x over previous
#include <cuda_runtime.h>
#include <cuda_fp16.h>
#include <math.h>

#define T_STEPS 12
#define N_NODES 50000
#define E_EDGES 800000
#define C_DIM   128
#define H_DIM   128

#define TOTAL_CNT  (T_STEPS * N_NODES)            // 600000
#define TOTAL_ROWS (T_STEPS * N_NODES)            // 600000
#define NB_SCAN    ((TOTAL_CNT + 1023) / 1024)    // 586
#define N_TILES    ((TOTAL_ROWS + 127) / 128)     // 4688
#define X_ELEMS    (TOTAL_ROWS * 128)             // 76.8M

// ---------------- device scratch ----------------
__device__ int    g_counts [TOTAL_CNT];
__device__ int    g_cursor [TOTAL_CNT];
__device__ int    g_offsets[TOTAL_CNT + 1];
__device__ int    g_bsums  [1024];
__device__ int    g_bbase  [1024];
__device__ int    g_csr    [T_STEPS * E_EDGES];
__device__ float  g_dinv   [TOTAL_CNT];
__device__ __half g_bufX   [X_ELEMS];              // x converted to half
__device__ __half g_bufA   [X_ELEMS];
__device__ __half g_bufB   [X_ELEMS];
__device__ float  g_gseq   [T_STEPS * H_DIM];

// ---------------- helpers ----------------
__device__ __forceinline__ unsigned pack_h2(float a, float b) {
    __half2 h = __floats2half2_rn(a, b);
    return *(unsigned*)&h;
}
__device__ __forceinline__ void u4_to_f8(uint4 u, float* f) {
    float2 a = __half22float2(*(__half2*)&u.x);
    float2 b = __half22float2(*(__half2*)&u.y);
    float2 c = __half22float2(*(__half2*)&u.z);
    float2 d = __half22float2(*(__half2*)&u.w);
    f[0] = a.x; f[1] = a.y; f[2] = b.x; f[3] = b.y;
    f[4] = c.x; f[5] = c.y; f[6] = d.x; f[7] = d.y;
}
__device__ __forceinline__ uint4 f8_to_u4(const float* f) {
    uint4 u;
    u.x = pack_h2(f[0], f[1]); u.y = pack_h2(f[2], f[3]);
    u.z = pack_h2(f[4], f[5]); u.w = pack_h2(f[6], f[7]);
    return u;
}
__device__ __forceinline__ void cp_async16(void* dst, const void* src) {
    unsigned s = (unsigned)__cvta_generic_to_shared(dst);
    asm volatile("cp.async.ca.shared.global [%0], [%1], 16;" :: "r"(s), "l"(src));
}
#define CP_COMMIT() asm volatile("cp.async.commit_group;")
#define CP_WAIT(N)  asm volatile("cp.async.wait_group %0;" :: "n"(N))

// ---------------- fused: zero counters/gseq + convert x fp32 -> fp16 ----------------
__global__ void zero_x2h_kernel(const float* __restrict__ x) {
    int i = blockIdx.x * blockDim.x + threadIdx.x;   // one per float4
    if (i < X_ELEMS / 4) {
        float4 f = ((const float4*)x)[i];
        uint2 o;
        o.x = pack_h2(f.x, f.y);
        o.y = pack_h2(f.z, f.w);
        ((uint2*)g_bufX)[i] = o;
    }
    if (i < TOTAL_CNT) { g_counts[i] = 0; g_cursor[i] = 0; }
    if (i < T_STEPS * H_DIM) g_gseq[i] = 0.0f;
}

// ---------------- count degrees ----------------
__global__ void count_all_kernel(const int* __restrict__ ei_seq) {
    int g = blockIdx.x * blockDim.x + threadIdx.x;
    if (g >= T_STEPS * E_EDGES) return;
    int t = g / E_EDGES;
    int e = g - t * E_EDGES;
    int d = ei_seq[(size_t)t * 2 * E_EDGES + E_EDGES + e];
    atomicAdd(&g_counts[t * N_NODES + d], 1);
}

// ---------------- dinv directly from counts (before scan) ----------------
__global__ void dinv_kernel() {
    int i = blockIdx.x * blockDim.x + threadIdx.x;
    if (i < TOTAL_CNT) g_dinv[i] = rsqrtf((float)(g_counts[i] + 1));
}

// ---------------- hierarchical scan ----------------
__global__ void scan1_kernel() {
    __shared__ int wt[32];
    int lane = threadIdx.x & 31;
    int wid  = threadIdx.x >> 5;
    int gid  = blockIdx.x * 1024 + threadIdx.x;
    int v = (gid < TOTAL_CNT) ? g_counts[gid] : 0;
    int s = v;
    #pragma unroll
    for (int off = 1; off < 32; off <<= 1) {
        int u = __shfl_up_sync(0xFFFFFFFFu, s, off);
        if (lane >= off) s += u;
    }
    if (lane == 31) wt[wid] = s;
    __syncthreads();
    if (wid == 0) {
        int w = wt[lane];
        int ws = w;
        #pragma unroll
        for (int off = 1; off < 32; off <<= 1) {
            int u = __shfl_up_sync(0xFFFFFFFFu, ws, off);
            if (lane >= off) ws += u;
        }
        wt[lane] = ws - w;
    }
    __syncthreads();
    int excl = wt[wid] + (s - v);
    if (gid < TOTAL_CNT) g_offsets[gid] = excl;
    if (threadIdx.x == 1023) g_bsums[blockIdx.x] = excl + v;
}

__global__ void scan2_kernel() {
    __shared__ int wt[32];
    int lane = threadIdx.x & 31;
    int wid  = threadIdx.x >> 5;
    int i = threadIdx.x;
    int v = (i < NB_SCAN) ? g_bsums[i] : 0;
    int s = v;
    #pragma unroll
    for (int off = 1; off < 32; off <<= 1) {
        int u = __shfl_up_sync(0xFFFFFFFFu, s, off);
        if (lane >= off) s += u;
    }
    if (lane == 31) wt[wid] = s;
    __syncthreads();
    if (wid == 0) {
        int w = wt[lane];
        int ws = w;
        #pragma unroll
        for (int off = 1; off < 32; off <<= 1) {
            int u = __shfl_up_sync(0xFFFFFFFFu, ws, off);
            if (lane >= off) ws += u;
        }
        wt[lane] = ws - w;
    }
    __syncthreads();
    g_bbase[i] = wt[wid] + (s - v);
}

__global__ void scan3_kernel() {
    int gid = blockIdx.x * 1024 + threadIdx.x;
    if (gid < TOTAL_CNT) g_offsets[gid] += g_bbase[blockIdx.x];
    if (gid == 0) g_offsets[TOTAL_CNT] = T_STEPS * E_EDGES;
}

// ---------------- fill CSR ----------------
__global__ void fill_all_kernel(const int* __restrict__ ei_seq) {
    int g = blockIdx.x * blockDim.x + threadIdx.x;
    if (g >= T_STEPS * E_EDGES) return;
    int t = g / E_EDGES;
    int e = g - t * E_EDGES;
    const int* base = ei_seq + (size_t)t * 2 * E_EDGES;
    int sv = base[e];
    int dv = base[E_EDGES + e];
    int f  = t * N_NODES + dv;
    int pos = g_offsets[f] + atomicAdd(&g_cursor[f], 1);
    g_csr[pos] = sv;
}

// ---------------- pipelined fp16 GEMM: Y(half) = diag(dinv) * (A @ W) ----------------
// W resident in smem for the whole block (4 tiles). A streamed via cp.async,
// 2-stage double buffer. mma.m16n8k16 f16 -> f32. A smem [128][12] words,
// conflict-free fragment loads; W smem [8][8][136] as half2(k,k+1) pairs.
__global__ __launch_bounds__(256, 2)
void gemm_f16_kernel(const __half* __restrict__ A,
                     const float* __restrict__ W,
                     const float* __restrict__ dinv,
                     __half* __restrict__ Y, int M)
{
    __shared__ unsigned Ws[8][8][136];   // [chunk][kpair][col]
    __shared__ unsigned As[2][128][12];  // [stage][row][kpair] (8 used, pad 12)

    const int tid  = threadIdx.x;
    const int lane = tid & 31;
    const int wid  = tid >> 5;
    const int wm   = wid & 3;
    const int wn   = wid >> 2;
    const int g    = lane >> 2;
    const int tig  = lane & 3;

    // ---- load W once per block ----
    #pragma unroll
    for (int i = 0; i < 32; i++) {
        int idx = tid + i * 256;      // 0..8191
        int pr  = idx >> 7;           // k-pair row 0..63
        int col = idx & 127;
        float w0 = W[(size_t)(2 * pr)     * 128 + col];
        float w1 = W[(size_t)(2 * pr + 1) * 128 + col];
        Ws[pr >> 3][pr & 7][col] = pack_h2(w0, w1);
    }
    __syncthreads();

    const int am  = tid >> 1;            // row in tile
    const int akw = (tid & 1) * 4;       // word offset (0 or 4) = k offset 0/8

    for (int tile = blockIdx.x; tile < N_TILES; tile += gridDim.x) {
        const int row0 = tile * 128;
        int agr = row0 + am;
        if (agr >= M) agr = 0;           // clamp (garbage never stored)
        const __half* Asrc = A + (size_t)agr * 128 + akw * 2;

        // prologue: chunk 0 -> stage 0
        cp_async16(&As[0][am][akw], Asrc);
        CP_COMMIT();

        float acc[2][8][4];
        #pragma unroll
        for (int mi = 0; mi < 2; mi++)
            #pragma unroll
            for (int ni = 0; ni < 8; ni++)
                #pragma unroll
                for (int q = 0; q < 4; q++) acc[mi][ni][q] = 0.0f;

        #pragma unroll
        for (int c = 0; c < 8; c++) {
            if (c < 7) {
                cp_async16(&As[(c + 1) & 1][am][akw], Asrc + (c + 1) * 16);
                CP_COMMIT();
                CP_WAIT(1);
            } else {
                CP_WAIT(0);
            }
            __syncthreads();

            const int st = c & 1;
            unsigned afr[2][4];
            #pragma unroll
            for (int mi = 0; mi < 2; mi++) {
                int rm = wm * 32 + mi * 16;
                afr[mi][0] = As[st][rm + g    ][tig    ];
                afr[mi][1] = As[st][rm + g + 8][tig    ];
                afr[mi][2] = As[st][rm + g    ][tig + 4];
                afr[mi][3] = As[st][rm + g + 8][tig + 4];
            }
            unsigned bfr[8][2];
            #pragma unroll
            for (int ni = 0; ni < 8; ni++) {
                int cb = wn * 64 + ni * 8 + g;
                bfr[ni][0] = Ws[c][tig    ][cb];
                bfr[ni][1] = Ws[c][tig + 4][cb];
            }

            #pragma unroll
            for (int mi = 0; mi < 2; mi++)
                #pragma unroll
                for (int ni = 0; ni < 8; ni++) {
                    asm volatile(
                        "mma.sync.aligned.m16n8k16.row.col.f32.f16.f16.f32 "
                        "{%0,%1,%2,%3},{%4,%5,%6,%7},{%8,%9},{%0,%1,%2,%3};"
                        : "+f"(acc[mi][ni][0]), "+f"(acc[mi][ni][1]),
                          "+f"(acc[mi][ni][2]), "+f"(acc[mi][ni][3])
                        : "r"(afr[mi][0]), "r"(afr[mi][1]),
                          "r"(afr[mi][2]), "r"(afr[mi][3]),
                          "r"(bfr[ni][0]), "r"(bfr[ni][1]));
                }
            __syncthreads();
        }

        // epilogue: dinv scale + fp16 store
        #pragma unroll
        for (int mi = 0; mi < 2; mi++) {
            #pragma unroll
            for (int hh = 0; hh < 2; hh++) {
                int r = row0 + wm * 32 + mi * 16 + g + hh * 8;
                if (r < M) {
                    float d = dinv[r];
                    #pragma unroll
                    for (int ni = 0; ni < 8; ni++) {
                        int cc = wn * 64 + ni * 8 + 2 * tig;
                        __half2 h = __floats2half2_rn(d * acc[mi][ni][hh * 2 + 0],
                                                      d * acc[mi][ni][hh * 2 + 1]);
                        *(__half2*)(Y + (size_t)r * 128 + cc) = h;
                    }
                }
            }
        }
    }
}

// ---------------- layer-1 aggregation: half-warp (16 lanes) per node, uint4 rows ----------------
__global__ void agg_kernel(const __half* __restrict__ hpAll,
                           const float* __restrict__ bias,
                           const float* __restrict__ dinvAll,
                           const int* __restrict__ offsAll,
                           __half* __restrict__ outAll)
{
    int t    = blockIdx.y;
    int node = (blockIdx.x * blockDim.x + threadIdx.x) >> 4;
    int lane = threadIdx.x & 15;
    if (node >= N_NODES) return;

    const __half* hp   = hpAll   + (size_t)t * N_NODES * 128;
    const float*  dinv = dinvAll + (size_t)t * N_NODES;
    const int*    offs = offsAll + (size_t)t * N_NODES;
    __half*       out  = outAll  + (size_t)t * N_NODES * 128;

    float a[8];
    u4_to_f8(((const uint4*)(hp + (size_t)node * 128))[lane], a);   // self loop

    int s = offs[node];
    int e = offs[node + 1];
    int j = s;
    for (; j + 3 < e; j += 4) {
        int s0 = __ldg(&g_csr[j]);
        int s1 = __ldg(&g_csr[j + 1]);
        int s2 = __ldg(&g_csr[j + 2]);
        int s3 = __ldg(&g_csr[j + 3]);
        uint4 u0 = ((const uint4*)(hp + (size_t)s0 * 128))[lane];
        uint4 u1 = ((const uint4*)(hp + (size_t)s1 * 128))[lane];
        uint4 u2 = ((const uint4*)(hp + (size_t)s2 * 128))[lane];
        uint4 u3 = ((const uint4*)(hp + (size_t)s3 * 128))[lane];
        float v0[8], v1[8], v2[8], v3[8];
        u4_to_f8(u0, v0); u4_to_f8(u1, v1); u4_to_f8(u2, v2); u4_to_f8(u3, v3);
        #pragma unroll
        for (int q = 0; q < 8; q++) a[q] += (v0[q] + v1[q]) + (v2[q] + v3[q]);
    }
    for (; j < e; j++) {
        int src = __ldg(&g_csr[j]);
        float v[8];
        u4_to_f8(((const uint4*)(hp + (size_t)src * 128))[lane], v);
        #pragma unroll
        for (int q = 0; q < 8; q++) a[q] += v[q];
    }

    float d = dinv[node];
    float4 b0 = ((const float4*)bias)[lane * 2];
    float4 b1 = ((const float4*)bias)[lane * 2 + 1];
    float r[8];
    r[0] = fmaxf(fmaf(d, a[0], b0.x), 0.0f);
    r[1] = fmaxf(fmaf(d, a[1], b0.y), 0.0f);
    r[2] = fmaxf(fmaf(d, a[2], b0.z), 0.0f);
    r[3] = fmaxf(fmaf(d, a[3], b0.w), 0.0f);
    r[4] = fmaxf(fmaf(d, a[4], b1.x), 0.0f);
    r[5] = fmaxf(fmaf(d, a[5], b1.y), 0.0f);
    r[6] = fmaxf(fmaf(d, a[6], b1.z), 0.0f);
    r[7] = fmaxf(fmaf(d, a[7], b1.w), 0.0f);
    ((uint4*)(out + (size_t)node * 128))[lane] = f8_to_u4(r);
}

// ---------------- layer-2 agg + mean pool: half-warp per node, grid-stride ----------------
__global__ void agg_pool_kernel(const __half* __restrict__ hpAll,
                                const float* __restrict__ bias,
                                const float* __restrict__ dinvAll,
                                const int* __restrict__ offsAll,
                                float* __restrict__ gseq)
{
    __shared__ float sacc[128];
    int t    = blockIdx.y;
    int lane = threadIdx.x & 15;
    int ghw  = blockIdx.x * (blockDim.x >> 4) + (threadIdx.x >> 4);
    int nhw  = gridDim.x * (blockDim.x >> 4);

    const __half* hp   = hpAll   + (size_t)t * N_NODES * 128;
    const float*  dinv = dinvAll + (size_t)t * N_NODES;
    const int*    offs = offsAll + (size_t)t * N_NODES;
    float*        gt   = gseq + t * H_DIM;

    if (threadIdx.x < 128) sacc[threadIdx.x] = 0.0f;
    __syncthreads();

    float4 b0 = ((const float4*)bias)[lane * 2];
    float4 b1 = ((const float4*)bias)[lane * 2 + 1];
    float bb[8] = {b0.x, b0.y, b0.z, b0.w, b1.x, b1.y, b1.z, b1.w};
    float pool[8] = {0.f, 0.f, 0.f, 0.f, 0.f, 0.f, 0.f, 0.f};

    for (int node = ghw; node < N_NODES; node += nhw) {
        float a[8];
        u4_to_f8(((const uint4*)(hp + (size_t)node * 128))[lane], a);
        int s = offs[node];
        int e = offs[node + 1];
        int j = s;
        for (; j + 3 < e; j += 4) {
            int s0 = __ldg(&g_csr[j]);
            int s1 = __ldg(&g_csr[j + 1]);
            int s2 = __ldg(&g_csr[j + 2]);
            int s3 = __ldg(&g_csr[j + 3]);
            uint4 u0 = ((const uint4*)(hp + (size_t)s0 * 128))[lane];
            uint4 u1 = ((const uint4*)(hp + (size_t)s1 * 128))[lane];
            uint4 u2 = ((const uint4*)(hp + (size_t)s2 * 128))[lane];
            uint4 u3 = ((const uint4*)(hp + (size_t)s3 * 128))[lane];
            float v0[8], v1[8], v2[8], v3[8];
            u4_to_f8(u0, v0); u4_to_f8(u1, v1); u4_to_f8(u2, v2); u4_to_f8(u3, v3);
            #pragma unroll
            for (int q = 0; q < 8; q++) a[q] += (v0[q] + v1[q]) + (v2[q] + v3[q]);
        }
        for (; j < e; j++) {
            int src = __ldg(&g_csr[j]);
            float v[8];
            u4_to_f8(((const uint4*)(hp + (size_t)src * 128))[lane], v);
            #pragma unroll
            for (int q = 0; q < 8; q++) a[q] += v[q];
        }
        float d = dinv[node];
        #pragma unroll
        for (int q = 0; q < 8; q++)
            pool[q] += fmaxf(fmaf(d, a[q], bb[q]), 0.0f);
    }

    #pragma unroll
    for (int q = 0; q < 8; q++)
        atomicAdd(&sacc[lane * 8 + q], pool[q]);
    __syncthreads();
    if (threadIdx.x < 128)
        atomicAdd(&gt[threadIdx.x], sacc[threadIdx.x] * (1.0f / (float)N_NODES));
}

// ---------------- GRU over T steps + head ----------------
__global__ void gru_head_kernel(const float* __restrict__ W_ih,
                                const float* __restrict__ W_hh,
                                const float* __restrict__ b_ih,
                                const float* __restrict__ b_hh,
                                const float* __restrict__ W_head,
                                const float* __restrict__ b_head,
                                float* __restrict__ out)
{
    __shared__ float gbuf[128];
    __shared__ float hbuf[128];
    int j = threadIdx.x;
    hbuf[j] = 0.0f;
    __syncthreads();

    for (int t = 0; t < T_STEPS; t++) {
        gbuf[j] = g_gseq[t * H_DIM + j];
        __syncthreads();
        float gir = b_ih[j], giz = b_ih[128 + j], gin = b_ih[256 + j];
        float ghr = b_hh[j], ghz = b_hh[128 + j], ghn = b_hh[256 + j];
        const float* wi0 = W_ih + (size_t)j * 128;
        const float* wi1 = W_ih + (size_t)(128 + j) * 128;
        const float* wi2 = W_ih + (size_t)(256 + j) * 128;
        const float* wh0 = W_hh + (size_t)j * 128;
        const float* wh1 = W_hh + (size_t)(128 + j) * 128;
        const float* wh2 = W_hh + (size_t)(256 + j) * 128;
        #pragma unroll 4
        for (int k = 0; k < 128; k++) {
            float gk = gbuf[k], hk = hbuf[k];
            gir = fmaf(wi0[k], gk, gir);
            giz = fmaf(wi1[k], gk, giz);
            gin = fmaf(wi2[k], gk, gin);
            ghr = fmaf(wh0[k], hk, ghr);
            ghz = fmaf(wh1[k], hk, ghz);
            ghn = fmaf(wh2[k], hk, ghn);
        }
        float r  = 1.0f / (1.0f + expf(-(gir + ghr)));
        float z  = 1.0f / (1.0f + expf(-(giz + ghz)));
        float nn = tanhf(gin + r * ghn);
        float hn = (1.0f - z) * nn + z * hbuf[j];
        __syncthreads();
        hbuf[j] = hn;
        __syncthreads();
    }

    float o = b_head[j];
    const float* wr = W_head + (size_t)j * 128;
    #pragma unroll 4
    for (int k = 0; k < 128; k++) o = fmaf(wr[k], hbuf[k], o);
    out[j] = o;
}

// ---------------- launch ----------------
extern "C" void kernel_launch(void* const* d_in, const int* in_sizes, int n_in,
                              void* d_out, int out_size)
{
    const float* x_seq  = (const float*)d_in[0];
    const int*   ei_seq = (const int*)  d_in[1];
    const float* W1     = (const float*)d_in[2];
    const float* b1     = (const float*)d_in[3];
    const float* W2     = (const float*)d_in[4];
    const float* b2     = (const float*)d_in[5];
    const float* W_ih   = (const float*)d_in[6];
    const float* W_hh   = (const float*)d_in[7];
    const float* b_ih   = (const float*)d_in[8];
    const float* b_hh   = (const float*)d_in[9];
    const float* W_head = (const float*)d_in[10];
    const float* b_head = (const float*)d_in[11];
    float* out = (float*)d_out;

    __half* bufX;  cudaGetSymbolAddress((void**)&bufX, g_bufX);
    __half* bufA;  cudaGetSymbolAddress((void**)&bufA, g_bufA);
    __half* bufB;  cudaGetSymbolAddress((void**)&bufB, g_bufB);
    float*  dinv;  cudaGetSymbolAddress((void**)&dinv, g_dinv);
    int*    offs;  cudaGetSymbolAddress((void**)&offs, g_offsets);
    float*  gseq;  cudaGetSymbolAddress((void**)&gseq, g_gseq);

    const int GEB = (T_STEPS * E_EDGES + 255) / 256;   // edge grid
    const int GMB = 1172;                              // gemm blocks (4 tiles each)
    const int AGX = (N_NODES + 15) / 16;               // agg blocks per t
    const int APX = 416;                               // agg_pool blocks per t

    zero_x2h_kernel<<<(X_ELEMS / 4 + 255) / 256, 256>>>(x_seq);               // #0
    count_all_kernel<<<GEB, 256>>>(ei_seq);                                    // #1
    dinv_kernel<<<(TOTAL_CNT + 255) / 256, 256>>>();                           // #2
    gemm_f16_kernel<<<GMB, 256>>>(bufX, W1, dinv, bufA, TOTAL_ROWS);           // #3 (profiled)
    scan1_kernel<<<NB_SCAN, 1024>>>();                                         // #4
    scan2_kernel<<<1, 1024>>>();                                               // #5
    scan3_kernel<<<NB_SCAN, 1024>>>();                                         // #6
    fill_all_kernel<<<GEB, 256>>>(ei_seq);                                     // #7

    {
        dim3 g(AGX, T_STEPS);
        agg_kernel<<<g, 256>>>(bufA, b1, dinv, offs, bufB);                    // #8
    }
    gemm_f16_kernel<<<GMB, 256>>>(bufB, W2, dinv, bufA, TOTAL_ROWS);           // #9
    {
        dim3 g(APX, T_STEPS);
        agg_pool_kernel<<<g, 256>>>(bufA, b2, dinv, offs, gseq);               // #10
    }

    gru_head_kernel<<<1, 128>>>(W_ih, W_hh, b_ih, b_hh, W_head, b_head, out);  // #11
}

// round 7
// speedup vs baseline: 2.5163x; 1.0095x over previous
#include <cuda_runtime.h>
#include <cuda_fp16.h>
#include <math.h>

#define T_STEPS 12
#define N_NODES 50000
#define E_EDGES 800000
#define C_DIM   128
#define H_DIM   128

#define TOTAL_CNT  (T_STEPS * N_NODES)            // 600000
#define TOTAL_ROWS (T_STEPS * N_NODES)            // 600000
#define NB_SCAN    ((TOTAL_CNT + 1023) / 1024)    // 586
#define N_TILES    ((TOTAL_ROWS + 127) / 128)     // 4688
#define X_ELEMS    (TOTAL_ROWS * 128)             // 76.8M

// ---------------- device scratch ----------------
__device__ int    g_counts [TOTAL_CNT];
__device__ int    g_cursor [TOTAL_CNT];
__device__ int    g_offsets[TOTAL_CNT + 1];
__device__ int    g_bsums  [1024];
__device__ int    g_bbase  [1024];
__device__ int    g_csr    [T_STEPS * E_EDGES];
__device__ float  g_dinv   [TOTAL_CNT];
__device__ __half g_bufX   [X_ELEMS];
__device__ __half g_bufA   [X_ELEMS];
__device__ __half g_bufB   [X_ELEMS];
__device__ float  g_gseq   [T_STEPS * H_DIM];

// ---------------- helpers ----------------
__device__ __forceinline__ unsigned pack_h2(float a, float b) {
    __half2 h = __floats2half2_rn(a, b);
    return *(unsigned*)&h;
}
__device__ __forceinline__ void u2_to_f4(uint2 u, float* f) {
    float2 a = __half22float2(*(__half2*)&u.x);
    float2 b = __half22float2(*(__half2*)&u.y);
    f[0] = a.x; f[1] = a.y; f[2] = b.x; f[3] = b.y;
}
__device__ __forceinline__ void cp_async16(void* dst, const void* src) {
    unsigned s = (unsigned)__cvta_generic_to_shared(dst);
    asm volatile("cp.async.ca.shared.global [%0], [%1], 16;" :: "r"(s), "l"(src));
}
#define CP_COMMIT() asm volatile("cp.async.commit_group;")
#define CP_WAIT(N)  asm volatile("cp.async.wait_group %0;" :: "n"(N))

// ---------------- fused: zero counters/gseq + convert x fp32 -> fp16 ----------------
__global__ void zero_x2h_kernel(const float* __restrict__ x) {
    int i = blockIdx.x * blockDim.x + threadIdx.x;
    if (i < X_ELEMS / 4) {
        float4 f = ((const float4*)x)[i];
        uint2 o;
        o.x = pack_h2(f.x, f.y);
        o.y = pack_h2(f.z, f.w);
        ((uint2*)g_bufX)[i] = o;
    }
    if (i < TOTAL_CNT) { g_counts[i] = 0; g_cursor[i] = 0; }
    if (i < T_STEPS * H_DIM) g_gseq[i] = 0.0f;
}

// ---------------- count degrees ----------------
__global__ void count_all_kernel(const int* __restrict__ ei_seq) {
    int g = blockIdx.x * blockDim.x + threadIdx.x;
    if (g >= T_STEPS * E_EDGES) return;
    int t = g / E_EDGES;
    int e = g - t * E_EDGES;
    int d = ei_seq[(size_t)t * 2 * E_EDGES + E_EDGES + e];
    atomicAdd(&g_counts[t * N_NODES + d], 1);
}

// ---------------- dinv directly from counts ----------------
__global__ void dinv_kernel() {
    int i = blockIdx.x * blockDim.x + threadIdx.x;
    if (i < TOTAL_CNT) g_dinv[i] = rsqrtf((float)(g_counts[i] + 1));
}

// ---------------- hierarchical scan ----------------
__global__ void scan1_kernel() {
    __shared__ int wt[32];
    int lane = threadIdx.x & 31;
    int wid  = threadIdx.x >> 5;
    int gid  = blockIdx.x * 1024 + threadIdx.x;
    int v = (gid < TOTAL_CNT) ? g_counts[gid] : 0;
    int s = v;
    #pragma unroll
    for (int off = 1; off < 32; off <<= 1) {
        int u = __shfl_up_sync(0xFFFFFFFFu, s, off);
        if (lane >= off) s += u;
    }
    if (lane == 31) wt[wid] = s;
    __syncthreads();
    if (wid == 0) {
        int w = wt[lane];
        int ws = w;
        #pragma unroll
        for (int off = 1; off < 32; off <<= 1) {
            int u = __shfl_up_sync(0xFFFFFFFFu, ws, off);
            if (lane >= off) ws += u;
        }
        wt[lane] = ws - w;
    }
    __syncthreads();
    int excl = wt[wid] + (s - v);
    if (gid < TOTAL_CNT) g_offsets[gid] = excl;
    if (threadIdx.x == 1023) g_bsums[blockIdx.x] = excl + v;
}

__global__ void scan2_kernel() {
    __shared__ int wt[32];
    int lane = threadIdx.x & 31;
    int wid  = threadIdx.x >> 5;
    int i = threadIdx.x;
    int v = (i < NB_SCAN) ? g_bsums[i] : 0;
    int s = v;
    #pragma unroll
    for (int off = 1; off < 32; off <<= 1) {
        int u = __shfl_up_sync(0xFFFFFFFFu, s, off);
        if (lane >= off) s += u;
    }
    if (lane == 31) wt[wid] = s;
    __syncthreads();
    if (wid == 0) {
        int w = wt[lane];
        int ws = w;
        #pragma unroll
        for (int off = 1; off < 32; off <<= 1) {
            int u = __shfl_up_sync(0xFFFFFFFFu, ws, off);
            if (lane >= off) ws += u;
        }
        wt[lane] = ws - w;
    }
    __syncthreads();
    g_bbase[i] = wt[wid] + (s - v);
}

__global__ void scan3_kernel() {
    int gid = blockIdx.x * 1024 + threadIdx.x;
    if (gid < TOTAL_CNT) g_offsets[gid] += g_bbase[blockIdx.x];
    if (gid == 0) g_offsets[TOTAL_CNT] = T_STEPS * E_EDGES;
}

// ---------------- fill CSR ----------------
__global__ void fill_all_kernel(const int* __restrict__ ei_seq) {
    int g = blockIdx.x * blockDim.x + threadIdx.x;
    if (g >= T_STEPS * E_EDGES) return;
    int t = g / E_EDGES;
    int e = g - t * E_EDGES;
    const int* base = ei_seq + (size_t)t * 2 * E_EDGES;
    int sv = base[e];
    int dv = base[E_EDGES + e];
    int f  = t * N_NODES + dv;
    int pos = g_offsets[f] + atomicAdd(&g_cursor[f], 1);
    g_csr[pos] = sv;
}

// ---------------- pipelined fp16 GEMM (unchanged) ----------------
__global__ __launch_bounds__(256, 2)
void gemm_f16_kernel(const __half* __restrict__ A,
                     const float* __restrict__ W,
                     const float* __restrict__ dinv,
                     __half* __restrict__ Y, int M)
{
    __shared__ unsigned Ws[8][8][136];
    __shared__ unsigned As[2][128][12];

    const int tid  = threadIdx.x;
    const int lane = tid & 31;
    const int wid  = tid >> 5;
    const int wm   = wid & 3;
    const int wn   = wid >> 2;
    const int g    = lane >> 2;
    const int tig  = lane & 3;

    #pragma unroll
    for (int i = 0; i < 32; i++) {
        int idx = tid + i * 256;
        int pr  = idx >> 7;
        int col = idx & 127;
        float w0 = W[(size_t)(2 * pr)     * 128 + col];
        float w1 = W[(size_t)(2 * pr + 1) * 128 + col];
        Ws[pr >> 3][pr & 7][col] = pack_h2(w0, w1);
    }
    __syncthreads();

    const int am  = tid >> 1;
    const int akw = (tid & 1) * 4;

    for (int tile = blockIdx.x; tile < N_TILES; tile += gridDim.x) {
        const int row0 = tile * 128;
        int agr = row0 + am;
        if (agr >= M) agr = 0;
        const __half* Asrc = A + (size_t)agr * 128 + akw * 2;

        cp_async16(&As[0][am][akw], Asrc);
        CP_COMMIT();

        float acc[2][8][4];
        #pragma unroll
        for (int mi = 0; mi < 2; mi++)
            #pragma unroll
            for (int ni = 0; ni < 8; ni++)
                #pragma unroll
                for (int q = 0; q < 4; q++) acc[mi][ni][q] = 0.0f;

        #pragma unroll
        for (int c = 0; c < 8; c++) {
            if (c < 7) {
                cp_async16(&As[(c + 1) & 1][am][akw], Asrc + (c + 1) * 16);
                CP_COMMIT();
                CP_WAIT(1);
            } else {
                CP_WAIT(0);
            }
            __syncthreads();

            const int st = c & 1;
            unsigned afr[2][4];
            #pragma unroll
            for (int mi = 0; mi < 2; mi++) {
                int rm = wm * 32 + mi * 16;
                afr[mi][0] = As[st][rm + g    ][tig    ];
                afr[mi][1] = As[st][rm + g + 8][tig    ];
                afr[mi][2] = As[st][rm + g    ][tig + 4];
                afr[mi][3] = As[st][rm + g + 8][tig + 4];
            }
            unsigned bfr[8][2];
            #pragma unroll
            for (int ni = 0; ni < 8; ni++) {
                int cb = wn * 64 + ni * 8 + g;
                bfr[ni][0] = Ws[c][tig    ][cb];
                bfr[ni][1] = Ws[c][tig + 4][cb];
            }

            #pragma unroll
            for (int mi = 0; mi < 2; mi++)
                #pragma unroll
                for (int ni = 0; ni < 8; ni++) {
                    asm volatile(
                        "mma.sync.aligned.m16n8k16.row.col.f32.f16.f16.f32 "
                        "{%0,%1,%2,%3},{%4,%5,%6,%7},{%8,%9},{%0,%1,%2,%3};"
                        : "+f"(acc[mi][ni][0]), "+f"(acc[mi][ni][1]),
                          "+f"(acc[mi][ni][2]), "+f"(acc[mi][ni][3])
                        : "r"(afr[mi][0]), "r"(afr[mi][1]),
                          "r"(afr[mi][2]), "r"(afr[mi][3]),
                          "r"(bfr[ni][0]), "r"(bfr[ni][1]));
                }
            __syncthreads();
        }

        #pragma unroll
        for (int mi = 0; mi < 2; mi++) {
            #pragma unroll
            for (int hh = 0; hh < 2; hh++) {
                int r = row0 + wm * 32 + mi * 16 + g + hh * 8;
                if (r < M) {
                    float d = dinv[r];
                    #pragma unroll
                    for (int ni = 0; ni < 8; ni++) {
                        int cc = wn * 64 + ni * 8 + 2 * tig;
                        __half2 h = __floats2half2_rn(d * acc[mi][ni][hh * 2 + 0],
                                                      d * acc[mi][ni][hh * 2 + 1]);
                        *(__half2*)(Y + (size_t)r * 128 + cc) = h;
                    }
                }
            }
        }
    }
}

// ---------------- layer-1 aggregation: FULL WARP per node, uint2 lanes ----------------
// No intra-warp divergence (one edge loop per warp); 8-edge unroll -> MLP 8.
__global__ void agg_kernel(const __half* __restrict__ hpAll,
                           const float* __restrict__ bias,
                           const float* __restrict__ dinvAll,
                           const int* __restrict__ offsAll,
                           __half* __restrict__ outAll)
{
    int t    = blockIdx.y;
    int node = (blockIdx.x * blockDim.x + threadIdx.x) >> 5;
    int lane = threadIdx.x & 31;
    if (node >= N_NODES) return;

    const __half* hp   = hpAll   + (size_t)t * N_NODES * 128;
    const float*  dinv = dinvAll + (size_t)t * N_NODES;
    const int*    offs = offsAll + (size_t)t * N_NODES;
    __half*       out  = outAll  + (size_t)t * N_NODES * 128;

    float a[4];
    u2_to_f4(((const uint2*)(hp + (size_t)node * 128))[lane], a);  // self loop

    int s = offs[node];
    int e = offs[node + 1];
    int j = s;
    for (; j + 8 <= e; j += 8) {
        int idx[8];
        #pragma unroll
        for (int q = 0; q < 8; q++) idx[q] = __ldg(&g_csr[j + q]);   // warp-uniform -> bcast
        uint2 u[8];
        #pragma unroll
        for (int q = 0; q < 8; q++)
            u[q] = __ldg(&((const uint2*)(hp + (size_t)idx[q] * 128))[lane]);
        #pragma unroll
        for (int q = 0; q < 8; q++) {
            float v[4];
            u2_to_f4(u[q], v);
            a[0] += v[0]; a[1] += v[1]; a[2] += v[2]; a[3] += v[3];
        }
    }
    if (j + 4 <= e) {
        int idx[4];
        #pragma unroll
        for (int q = 0; q < 4; q++) idx[q] = __ldg(&g_csr[j + q]);
        uint2 u[4];
        #pragma unroll
        for (int q = 0; q < 4; q++)
            u[q] = __ldg(&((const uint2*)(hp + (size_t)idx[q] * 128))[lane]);
        #pragma unroll
        for (int q = 0; q < 4; q++) {
            float v[4];
            u2_to_f4(u[q], v);
            a[0] += v[0]; a[1] += v[1]; a[2] += v[2]; a[3] += v[3];
        }
        j += 4;
    }
    for (; j < e; j++) {
        int src = __ldg(&g_csr[j]);
        float v[4];
        u2_to_f4(((const uint2*)(hp + (size_t)src * 128))[lane], v);
        a[0] += v[0]; a[1] += v[1]; a[2] += v[2]; a[3] += v[3];
    }

    float  d = dinv[node];
    float4 b = ((const float4*)bias)[lane];
    uint2 o;
    o.x = pack_h2(fmaxf(fmaf(d, a[0], b.x), 0.0f), fmaxf(fmaf(d, a[1], b.y), 0.0f));
    o.y = pack_h2(fmaxf(fmaf(d, a[2], b.z), 0.0f), fmaxf(fmaf(d, a[3], b.w), 0.0f));
    ((uint2*)(out + (size_t)node * 128))[lane] = o;
}

// ---------------- layer-2 agg + mean pool: FULL WARP per node, grid-stride ----------------
__global__ void agg_pool_kernel(const __half* __restrict__ hpAll,
                                const float* __restrict__ bias,
                                const float* __restrict__ dinvAll,
                                const int* __restrict__ offsAll,
                                float* __restrict__ gseq)
{
    __shared__ float sacc[128];
    int t    = blockIdx.y;
    int lane = threadIdx.x & 31;
    int gw   = blockIdx.x * (blockDim.x >> 5) + (threadIdx.x >> 5);
    int nw   = gridDim.x * (blockDim.x >> 5);

    const __half* hp   = hpAll   + (size_t)t * N_NODES * 128;
    const float*  dinv = dinvAll + (size_t)t * N_NODES;
    const int*    offs = offsAll + (size_t)t * N_NODES;
    float*        gt   = gseq + t * H_DIM;

    if (threadIdx.x < 128) sacc[threadIdx.x] = 0.0f;
    __syncthreads();

    float4 bq = ((const float4*)bias)[lane];
    float pool[4] = {0.f, 0.f, 0.f, 0.f};

    for (int node = gw; node < N_NODES; node += nw) {
        float a[4];
        u2_to_f4(((const uint2*)(hp + (size_t)node * 128))[lane], a);
        int s = offs[node];
        int e = offs[node + 1];
        int j = s;
        for (; j + 8 <= e; j += 8) {
            int idx[8];
            #pragma unroll
            for (int q = 0; q < 8; q++) idx[q] = __ldg(&g_csr[j + q]);
            uint2 u[8];
            #pragma unroll
            for (int q = 0; q < 8; q++)
                u[q] = __ldg(&((const uint2*)(hp + (size_t)idx[q] * 128))[lane]);
            #pragma unroll
            for (int q = 0; q < 8; q++) {
                float v[4];
                u2_to_f4(u[q], v);
                a[0] += v[0]; a[1] += v[1]; a[2] += v[2]; a[3] += v[3];
            }
        }
        if (j + 4 <= e) {
            int idx[4];
            #pragma unroll
            for (int q = 0; q < 4; q++) idx[q] = __ldg(&g_csr[j + q]);
            uint2 u[4];
            #pragma unroll
            for (int q = 0; q < 4; q++)
                u[q] = __ldg(&((const uint2*)(hp + (size_t)idx[q] * 128))[lane]);
            #pragma unroll
            for (int q = 0; q < 4; q++) {
                float v[4];
                u2_to_f4(u[q], v);
                a[0] += v[0]; a[1] += v[1]; a[2] += v[2]; a[3] += v[3];
            }
            j += 4;
        }
        for (; j < e; j++) {
            int src = __ldg(&g_csr[j]);
            float v[4];
            u2_to_f4(((const uint2*)(hp + (size_t)src * 128))[lane], v);
            a[0] += v[0]; a[1] += v[1]; a[2] += v[2]; a[3] += v[3];
        }
        float d = dinv[node];
        pool[0] += fmaxf(fmaf(d, a[0], bq.x), 0.0f);
        pool[1] += fmaxf(fmaf(d, a[1], bq.y), 0.0f);
        pool[2] += fmaxf(fmaf(d, a[2], bq.z), 0.0f);
        pool[3] += fmaxf(fmaf(d, a[3], bq.w), 0.0f);
    }

    #pragma unroll
    for (int q = 0; q < 4; q++)
        atomicAdd(&sacc[lane * 4 + q], pool[q]);
    __syncthreads();
    if (threadIdx.x < 128)
        atomicAdd(&gt[threadIdx.x], sacc[threadIdx.x] * (1.0f / (float)N_NODES));
}

// ---------------- GRU over T steps + head ----------------
__global__ void gru_head_kernel(const float* __restrict__ W_ih,
                                const float* __restrict__ W_hh,
                                const float* __restrict__ b_ih,
                                const float* __restrict__ b_hh,
                                const float* __restrict__ W_head,
                                const float* __restrict__ b_head,
                                float* __restrict__ out)
{
    __shared__ float gbuf[128];
    __shared__ float hbuf[128];
    int j = threadIdx.x;
    hbuf[j] = 0.0f;
    __syncthreads();

    for (int t = 0; t < T_STEPS; t++) {
        gbuf[j] = g_gseq[t * H_DIM + j];
        __syncthreads();
        float gir = b_ih[j], giz = b_ih[128 + j], gin = b_ih[256 + j];
        float ghr = b_hh[j], ghz = b_hh[128 + j], ghn = b_hh[256 + j];
        const float* wi0 = W_ih + (size_t)j * 128;
        const float* wi1 = W_ih + (size_t)(128 + j) * 128;
        const float* wi2 = W_ih + (size_t)(256 + j) * 128;
        const float* wh0 = W_hh + (size_t)j * 128;
        const float* wh1 = W_hh + (size_t)(128 + j) * 128;
        const float* wh2 = W_hh + (size_t)(256 + j) * 128;
        #pragma unroll 4
        for (int k = 0; k < 128; k++) {
            float gk = gbuf[k], hk = hbuf[k];
            gir = fmaf(wi0[k], gk, gir);
            giz = fmaf(wi1[k], gk, giz);
            gin = fmaf(wi2[k], gk, gin);
            ghr = fmaf(wh0[k], hk, ghr);
            ghz = fmaf(wh1[k], hk, ghz);
            ghn = fmaf(wh2[k], hk, ghn);
        }
        float r  = 1.0f / (1.0f + expf(-(gir + ghr)));
        float z  = 1.0f / (1.0f + expf(-(giz + ghz)));
        float nn = tanhf(gin + r * ghn);
        float hn = (1.0f - z) * nn + z * hbuf[j];
        __syncthreads();
        hbuf[j] = hn;
        __syncthreads();
    }

    float o = b_head[j];
    const float* wr = W_head + (size_t)j * 128;
    #pragma unroll 4
    for (int k = 0; k < 128; k++) o = fmaf(wr[k], hbuf[k], o);
    out[j] = o;
}

// ---------------- launch ----------------
extern "C" void kernel_launch(void* const* d_in, const int* in_sizes, int n_in,
                              void* d_out, int out_size)
{
    const float* x_seq  = (const float*)d_in[0];
    const int*   ei_seq = (const int*)  d_in[1];
    const float* W1     = (const float*)d_in[2];
    const float* b1     = (const float*)d_in[3];
    const float* W2     = (const float*)d_in[4];
    const float* b2     = (const float*)d_in[5];
    const float* W_ih   = (const float*)d_in[6];
    const float* W_hh   = (const float*)d_in[7];
    const float* b_ih   = (const float*)d_in[8];
    const float* b_hh   = (const float*)d_in[9];
    const float* W_head = (const float*)d_in[10];
    const float* b_head = (const float*)d_in[11];
    float* out = (float*)d_out;

    __half* bufX;  cudaGetSymbolAddress((void**)&bufX, g_bufX);
    __half* bufA;  cudaGetSymbolAddress((void**)&bufA, g_bufA);
    __half* bufB;  cudaGetSymbolAddress((void**)&bufB, g_bufB);
    float*  dinv;  cudaGetSymbolAddress((void**)&dinv, g_dinv);
    int*    offs;  cudaGetSymbolAddress((void**)&offs, g_offsets);
    float*  gseq;  cudaGetSymbolAddress((void**)&gseq, g_gseq);

    const int GEB = (T_STEPS * E_EDGES + 255) / 256;
    const int GMB = 1172;
    const int AGX = (N_NODES * 32 + 255) / 256;        // warp per node
    const int APX = 416;

    zero_x2h_kernel<<<(X_ELEMS / 4 + 255) / 256, 256>>>(x_seq);               // #0
    count_all_kernel<<<GEB, 256>>>(ei_seq);                                    // #1
    dinv_kernel<<<(TOTAL_CNT + 255) / 256, 256>>>();                           // #2
    gemm_f16_kernel<<<GMB, 256>>>(bufX, W1, dinv, bufA, TOTAL_ROWS);           // #3 (profiled)
    scan1_kernel<<<NB_SCAN, 1024>>>();                                         // #4
    scan2_kernel<<<1, 1024>>>();                                               // #5
    scan3_kernel<<<NB_SCAN, 1024>>>();                                         // #6
    fill_all_kernel<<<GEB, 256>>>(ei_seq);                                     // #7

    {
        dim3 g(AGX, T_STEPS);
        agg_kernel<<<g, 256>>>(bufA, b1, dinv, offs, bufB);                    // #8
    }
    gemm_f16_kernel<<<GMB, 256>>>(bufB, W2, dinv, bufA, TOTAL_ROWS);           // #9
    {
        dim3 g(APX, T_STEPS);
        agg_pool_kernel<<<g, 256>>>(bufA, b2, dinv, offs, gseq);               // #10
    }

    gru_head_kernel<<<1, 128>>>(W_ih, W_hh, b_ih, b_hh, W_head, b_head, out);  // #11
}